// round 1
// baseline (speedup 1.0000x reference)
#include <cuda_runtime.h>
#include <math.h>

#define Nn 100000
#define Ee 1600000
#define Hh 128
#define Gg 512
#define TDd 256

// Scratch (device globals — no allocation allowed)
__device__ float g_agg[(size_t)Nn * Hh];   // x + scatter-sum(msg)
__device__ float g_h[(size_t)Nn * Hh];     // post-MLP h
__device__ float g_mean[Gg * Hh];          // mean*mean_scale (pre-multiplied)
__device__ float g_rstd[Gg * Hh];
__device__ float g_gamma[Gg * Hh];
__device__ float g_beta[Gg * Hh];

__device__ __forceinline__ float silu_f(float v) {
    return v * (1.0f / (1.0f + __expf(-v)));
}

// ---------------------------------------------------------------------------
// 1) init: g_agg = x   (h_pre = x + agg, so seed accumulator with x)
// ---------------------------------------------------------------------------
__global__ void copy_kernel(const float* __restrict__ x) {
    size_t i = (size_t)blockIdx.x * blockDim.x + threadIdx.x;  // float4 index
    ((float4*)g_agg)[i] = ((const float4*)x)[i];
}

// ---------------------------------------------------------------------------
// 2) edge kernel: fused GEMM (edge_attr @ We) + gather x[src] + relu + scatter
//    tile: 128 edges x 128 feats, K=32.  256 threads, 8x8 microtile.
// ---------------------------------------------------------------------------
__global__ __launch_bounds__(256) void edge_kernel(
    const float* __restrict__ x, const int* __restrict__ ei,
    const float* __restrict__ ea, const float* __restrict__ We,
    const float* __restrict__ be) {
    __shared__ float Bs[32][132];   // We[k][n]
    __shared__ float As[128][36];   // edge_attr[m][k]
    __shared__ float be_s[128];

    const int tid = threadIdx.x;
    const int e0 = blockIdx.x * 128;

    for (int i = tid; i < 32 * 128; i += 256) Bs[i >> 7][i & 127] = We[i];
    if (tid < 128) be_s[tid] = be[tid];
    // load 128 edges x 32 attrs (1024 float4)
    for (int i = tid; i < 1024; i += 256) {
        int m = i >> 3, k4 = (i & 7) * 4;
        float4 v = *(const float4*)&ea[(size_t)(e0 + m) * 32 + k4];
        *(float4*)&As[m][k4] = v;
    }
    __syncthreads();

    const int tx = tid & 15, ty = tid >> 4;
    const int m0 = ty * 8, n0 = tx * 8;

    float acc[8][8];
#pragma unroll
    for (int i = 0; i < 8; ++i)
#pragma unroll
        for (int j = 0; j < 8; ++j) acc[i][j] = 0.f;

#pragma unroll
    for (int k = 0; k < 32; ++k) {
        float b[8];
        *(float4*)&b[0] = *(const float4*)&Bs[k][n0];
        *(float4*)&b[4] = *(const float4*)&Bs[k][n0 + 4];
#pragma unroll
        for (int i = 0; i < 8; ++i) {
            float a = As[m0 + i][k];
#pragma unroll
            for (int j = 0; j < 8; ++j) acc[i][j] += a * b[j];
        }
    }

    float bb0[8];
#pragma unroll
    for (int j = 0; j < 8; ++j) bb0[j] = be_s[n0 + j];

#pragma unroll
    for (int i = 0; i < 8; ++i) {
        int e = e0 + m0 + i;
        int s = ei[e];
        int d = ei[Ee + e];
        const float* xr = x + (size_t)s * 128 + n0;
        float4 x1 = *(const float4*)xr;
        float4 x2 = *(const float4*)(xr + 4);
        float r0 = fmaxf(x1.x + acc[i][0] + bb0[0], 0.f);
        float r1 = fmaxf(x1.y + acc[i][1] + bb0[1], 0.f);
        float r2 = fmaxf(x1.z + acc[i][2] + bb0[2], 0.f);
        float r3 = fmaxf(x1.w + acc[i][3] + bb0[3], 0.f);
        float r4 = fmaxf(x2.x + acc[i][4] + bb0[4], 0.f);
        float r5 = fmaxf(x2.y + acc[i][5] + bb0[5], 0.f);
        float r6 = fmaxf(x2.z + acc[i][6] + bb0[6], 0.f);
        float r7 = fmaxf(x2.w + acc[i][7] + bb0[7], 0.f);
        float* dp = g_agg + (size_t)d * 128 + n0;
        asm volatile("red.global.add.v4.f32 [%0], {%1,%2,%3,%4};"
                     :: "l"(dp), "f"(r0), "f"(r1), "f"(r2), "f"(r3) : "memory");
        asm volatile("red.global.add.v4.f32 [%0], {%1,%2,%3,%4};"
                     :: "l"(dp + 4), "f"(r4), "f"(r5), "f"(r6), "f"(r7) : "memory");
    }
}

// ---------------------------------------------------------------------------
// 3) fused node MLP:  g_h = silu(g_agg @ W1 + b1) @ W2 + b2
//    tile: 128 nodes x 128 feats, K=128 streamed in 32-chunks.
// ---------------------------------------------------------------------------
#define MLP_SMEM ((128 * 132 + 32 * 132) * 4)

extern "C" __global__ __launch_bounds__(256) void mlp_kernel(
    const float* __restrict__ W1, const float* __restrict__ b1,
    const float* __restrict__ W2, const float* __restrict__ b2) {
    extern __shared__ float smem[];
    float* As = smem;             // [128][132] : A[m][k]
    float* Ws = smem + 128 * 132; // [32][132]  : W[k][n] chunk

    const int tid = threadIdx.x;
    const int r0 = blockIdx.x * 128;

    for (int i = tid; i < 128 * 32; i += 256) {
        int m = i >> 5, k4 = (i & 31) * 4;
        int node = r0 + m;
        float4 v = make_float4(0.f, 0.f, 0.f, 0.f);
        if (node < Nn) v = *(const float4*)&g_agg[(size_t)node * 128 + k4];
        *(float4*)&As[m * 132 + k4] = v;
    }

    const int tx = tid & 15, ty = tid >> 4;
    const int m0 = ty * 8, n0 = tx * 8;

    float acc[8][8];
#pragma unroll
    for (int i = 0; i < 8; ++i)
#pragma unroll
        for (int j = 0; j < 8; ++j) acc[i][j] = 0.f;

    // ---- layer 1 ----
    for (int kc = 0; kc < 128; kc += 32) {
        __syncthreads();
        for (int i = tid; i < 32 * 32; i += 256) {
            int kk = i >> 5, c4 = (i & 31) * 4;
            *(float4*)&Ws[kk * 132 + c4] = *(const float4*)&W1[(size_t)(kc + kk) * 128 + c4];
        }
        __syncthreads();
#pragma unroll
        for (int kk = 0; kk < 32; ++kk) {
            int k = kc + kk;
            float b[8];
            *(float4*)&b[0] = *(const float4*)&Ws[kk * 132 + n0];
            *(float4*)&b[4] = *(const float4*)&Ws[kk * 132 + n0 + 4];
#pragma unroll
            for (int i = 0; i < 8; ++i) {
                float a = As[(m0 + i) * 132 + k];
#pragma unroll
                for (int j = 0; j < 8; ++j) acc[i][j] += a * b[j];
            }
        }
    }

    // mid = silu(acc + b1)  -> back into As (same [m][k] layout, k = feature)
    __syncthreads();
#pragma unroll
    for (int i = 0; i < 8; ++i) {
        float t[8];
#pragma unroll
        for (int j = 0; j < 8; ++j) {
            float v = acc[i][j] + b1[n0 + j];
            t[j] = silu_f(v);
            acc[i][j] = 0.f;
        }
        *(float4*)&As[(m0 + i) * 132 + n0] = *(float4*)&t[0];
        *(float4*)&As[(m0 + i) * 132 + n0 + 4] = *(float4*)&t[4];
    }

    // ---- layer 2 ----
    for (int kc = 0; kc < 128; kc += 32) {
        __syncthreads();
        for (int i = tid; i < 32 * 32; i += 256) {
            int kk = i >> 5, c4 = (i & 31) * 4;
            *(float4*)&Ws[kk * 132 + c4] = *(const float4*)&W2[(size_t)(kc + kk) * 128 + c4];
        }
        __syncthreads();
#pragma unroll
        for (int kk = 0; kk < 32; ++kk) {
            int k = kc + kk;
            float b[8];
            *(float4*)&b[0] = *(const float4*)&Ws[kk * 132 + n0];
            *(float4*)&b[4] = *(const float4*)&Ws[kk * 132 + n0 + 4];
#pragma unroll
            for (int i = 0; i < 8; ++i) {
                float a = As[(m0 + i) * 132 + k];
#pragma unroll
                for (int j = 0; j < 8; ++j) acc[i][j] += a * b[j];
            }
        }
    }

#pragma unroll
    for (int i = 0; i < 8; ++i) {
        int node = r0 + m0 + i;
        if (node < Nn) {
            float t[8];
#pragma unroll
            for (int j = 0; j < 8; ++j) t[j] = acc[i][j] + b2[n0 + j];
            *(float4*)&g_h[(size_t)node * 128 + n0] = *(float4*)&t[0];
            *(float4*)&g_h[(size_t)node * 128 + n0 + 4] = *(float4*)&t[4];
        }
    }
}

// ---------------------------------------------------------------------------
// 4) GraphNorm stats: one pass (sum, sumsq) per graph; batch is sorted.
//    g_mean stores mean*mean_scale (the subtrahend), g_rstd = rsqrt(var+eps).
// ---------------------------------------------------------------------------
__global__ void stats_kernel(const int* __restrict__ batch,
                             const float* __restrict__ ms) {
    __shared__ int bounds[2];
    const int g = blockIdx.x;
    if (threadIdx.x < 2) {
        int target = g + threadIdx.x;  // lower_bound(batch, target)
        int lo = 0, hi = Nn;
        while (lo < hi) {
            int mid = (lo + hi) >> 1;
            if (batch[mid] < target) lo = mid + 1; else hi = mid;
        }
        bounds[threadIdx.x] = lo;
    }
    __syncthreads();
    const int s = bounds[0], e = bounds[1];
    const int f = threadIdx.x;  // 128 threads

    float sum0 = 0.f, sq0 = 0.f, sum1 = 0.f, sq1 = 0.f;
    int n = s;
    for (; n + 1 < e; n += 2) {
        float v0 = g_h[(size_t)n * 128 + f];
        float v1 = g_h[(size_t)(n + 1) * 128 + f];
        sum0 += v0; sq0 += v0 * v0;
        sum1 += v1; sq1 += v1 * v1;
    }
    if (n < e) {
        float v0 = g_h[(size_t)n * 128 + f];
        sum0 += v0; sq0 += v0 * v0;
    }
    float sum = sum0 + sum1, sq = sq0 + sq1;

    float c = fmaxf((float)(e - s), 1.f);
    float mean = sum / c;
    float m2 = sq / c;
    float msf = ms[f];
    float var = m2 - (2.f * msf - msf * msf) * mean * mean;
    var = fmaxf(var, 0.f);
    g_mean[g * 128 + f] = mean * msf;
    g_rstd[g * 128 + f] = rsqrtf(var + 1e-5f);
}

// ---------------------------------------------------------------------------
// 5) FiLM params: gamma = te@Wg + bg + 1, beta = te@Wb + bb   (tiny)
// ---------------------------------------------------------------------------
__global__ void film_kernel(const float* __restrict__ te,
                            const float* __restrict__ Wg, const float* __restrict__ bg,
                            const float* __restrict__ Wb, const float* __restrict__ bb) {
    __shared__ float t[256];
    const int g = blockIdx.x, f = threadIdx.x;  // 128 threads
    for (int i = f; i < 256; i += 128) t[i] = te[(size_t)g * 256 + i];
    __syncthreads();
    float ag = 0.f, ab = 0.f;
#pragma unroll 8
    for (int k = 0; k < 256; ++k) {
        float tv = t[k];
        ag += tv * Wg[(size_t)k * 128 + f];
        ab += tv * Wb[(size_t)k * 128 + f];
    }
    g_gamma[g * 128 + f] = ag + bg[f] + 1.f;
    g_beta[g * 128 + f] = ab + bb[f];
}

// ---------------------------------------------------------------------------
// 6) final: out = x + silu(gamma*(gnw*((h - mean*ms)*rstd) + gnb) + beta)
// ---------------------------------------------------------------------------
__global__ void final_kernel(const float* __restrict__ x,
                             const int* __restrict__ batch,
                             const float* __restrict__ gnw,
                             const float* __restrict__ gnb,
                             float* __restrict__ out) {
    int i = blockIdx.x * blockDim.x + threadIdx.x;  // float4 index
    int n = i >> 5;
    int f4 = (i & 31) * 4;
    int g = batch[n];

    float4 h4 = *(float4*)&g_h[(size_t)n * 128 + f4];
    float4 x4 = *(const float4*)&x[(size_t)n * 128 + f4];
    float4 mn = *(float4*)&g_mean[g * 128 + f4];
    float4 rs = *(float4*)&g_rstd[g * 128 + f4];
    float4 gm = *(float4*)&g_gamma[g * 128 + f4];
    float4 bt = *(float4*)&g_beta[g * 128 + f4];
    float4 w4 = *(const float4*)&gnw[f4];
    float4 b4 = *(const float4*)&gnb[f4];

    float4 o;
    {
        float v = gm.x * (w4.x * ((h4.x - mn.x) * rs.x) + b4.x) + bt.x;
        o.x = x4.x + silu_f(v);
    }
    {
        float v = gm.y * (w4.y * ((h4.y - mn.y) * rs.y) + b4.y) + bt.y;
        o.y = x4.y + silu_f(v);
    }
    {
        float v = gm.z * (w4.z * ((h4.z - mn.z) * rs.z) + b4.z) + bt.z;
        o.z = x4.z + silu_f(v);
    }
    {
        float v = gm.w * (w4.w * ((h4.w - mn.w) * rs.w) + b4.w) + bt.w;
        o.w = x4.w + silu_f(v);
    }
    *(float4*)&out[(size_t)n * 128 + f4] = o;
}

// ---------------------------------------------------------------------------
extern "C" void kernel_launch(void* const* d_in, const int* in_sizes, int n_in,
                              void* d_out, int out_size) {
    const float* x   = (const float*)d_in[0];
    const int*   ei  = (const int*)d_in[1];
    const float* ea  = (const float*)d_in[2];
    const int*   bat = (const int*)d_in[3];
    const float* te  = (const float*)d_in[4];
    const float* We  = (const float*)d_in[5];
    const float* be  = (const float*)d_in[6];
    const float* W1  = (const float*)d_in[7];
    const float* b1  = (const float*)d_in[8];
    const float* W2  = (const float*)d_in[9];
    const float* b2  = (const float*)d_in[10];
    const float* gnw = (const float*)d_in[11];
    const float* gnb = (const float*)d_in[12];
    const float* gms = (const float*)d_in[13];
    const float* Wg  = (const float*)d_in[14];
    const float* bg  = (const float*)d_in[15];
    const float* Wb  = (const float*)d_in[16];
    const float* bb  = (const float*)d_in[17];
    float* out = (float*)d_out;

    cudaFuncSetAttribute((const void*)mlp_kernel,
                         cudaFuncAttributeMaxDynamicSharedMemorySize, MLP_SMEM);

    copy_kernel<<<12500, 256>>>(x);                       // N*H/4 = 3.2M float4
    edge_kernel<<<Ee / 128, 256>>>(x, ei, ea, We, be);    // 12500 blocks
    mlp_kernel<<<(Nn + 127) / 128, 256, MLP_SMEM>>>(W1, b1, W2, b2);
    film_kernel<<<Gg, 128>>>(te, Wg, bg, Wb, bb);
    stats_kernel<<<Gg, 128>>>(bat, gms);
    final_kernel<<<12500, 256>>>(x, bat, gnw, gnb, out);  // N*H/4 float4
}

// round 2
// speedup vs baseline: 1.1929x; 1.1929x over previous
#include <cuda_runtime.h>
#include <math.h>

#define Nn 100000
#define Ee 1600000
#define Hh 128
#define Gg 512
#define TDd 256

typedef unsigned long long ull;

// Scratch (device globals — no allocation allowed)
__device__ float g_agg[(size_t)Nn * Hh];   // x + scatter-sum(msg)
__device__ float g_h[(size_t)Nn * Hh];     // post-MLP h
__device__ float g_mean[Gg * Hh];          // mean*mean_scale (pre-multiplied)
__device__ float g_rstd[Gg * Hh];
__device__ float g_gamma[Gg * Hh];
__device__ float g_beta[Gg * Hh];

__device__ __forceinline__ float silu_f(float v) {
    return v * (1.0f / (1.0f + __expf(-v)));
}

// ---- packed f32x2 helpers (Blackwell FFMA2) --------------------------------
__device__ __forceinline__ ull pack2(float x, float y) {
    ull r;
    asm("mov.b64 %0, {%1, %2};" : "=l"(r) : "f"(x), "f"(y));
    return r;
}
__device__ __forceinline__ void ffma2(ull& d, ull a, ull b) {
    asm("fma.rn.f32x2 %0, %1, %2, %0;" : "+l"(d) : "l"(a), "l"(b));
}
__device__ __forceinline__ float2 unpack2(ull v) {
    float2 r;
    asm("mov.b64 {%0, %1}, %2;" : "=f"(r.x), "=f"(r.y) : "l"(v));
    return r;
}

// ---------------------------------------------------------------------------
// 1) init: g_agg = x
// ---------------------------------------------------------------------------
__global__ void copy_kernel(const float* __restrict__ x) {
    size_t i = (size_t)blockIdx.x * blockDim.x + threadIdx.x;  // float4 index
    ((float4*)g_agg)[i] = ((const float4*)x)[i];
}

// ---------------------------------------------------------------------------
// 2) edge kernel: fused GEMM (edge_attr @ We) + gather x[src] + relu + scatter
//    tile: 128 edges x 128 feats, K=32.  256 threads, 8x8 microtile, FFMA2.
// ---------------------------------------------------------------------------
__global__ __launch_bounds__(256) void edge_kernel(
    const float* __restrict__ x, const int* __restrict__ ei,
    const float* __restrict__ ea, const float* __restrict__ We,
    const float* __restrict__ be) {
    __shared__ float Bs[32][132];   // We[k][n]
    __shared__ float As[32][132];   // edge_attr transposed: As[k][m]
    __shared__ float be_s[128];
    __shared__ int src_s[128];
    __shared__ int dst_s[128];

    const int tid = threadIdx.x;
    const int e0 = blockIdx.x * 128;

    for (int i = tid; i < 32 * 128; i += 256) Bs[i >> 7][i & 127] = We[i];
    if (tid < 128) {
        be_s[tid] = be[tid];
        src_s[tid] = ei[e0 + tid];
    } else {
        dst_s[tid - 128] = ei[Ee + e0 + (tid - 128)];
    }
    // load 128 edges x 32 attrs, transpose into As[k][m]
    for (int i = tid; i < 1024; i += 256) {
        int m = i >> 3, k4 = (i & 7) * 4;
        float4 v = *(const float4*)&ea[(size_t)(e0 + m) * 32 + k4];
        As[k4 + 0][m] = v.x;
        As[k4 + 1][m] = v.y;
        As[k4 + 2][m] = v.z;
        As[k4 + 3][m] = v.w;
    }
    __syncthreads();

    const int tx = tid & 15, ty = tid >> 4;
    const int m0 = ty * 8, n0 = tx * 8;

    ull acc[8][4];
#pragma unroll
    for (int i = 0; i < 8; ++i)
#pragma unroll
        for (int j = 0; j < 4; ++j) acc[i][j] = 0ULL;

#pragma unroll
    for (int k = 0; k < 32; ++k) {
        float a[8];
        *(float4*)&a[0] = *(const float4*)&As[k][m0];
        *(float4*)&a[4] = *(const float4*)&As[k][m0 + 4];
        ulonglong2 bv0 = *(const ulonglong2*)&Bs[k][n0];
        ulonglong2 bv1 = *(const ulonglong2*)&Bs[k][n0 + 4];
#pragma unroll
        for (int i = 0; i < 8; ++i) {
            ull av = pack2(a[i], a[i]);
            ffma2(acc[i][0], av, bv0.x);
            ffma2(acc[i][1], av, bv0.y);
            ffma2(acc[i][2], av, bv1.x);
            ffma2(acc[i][3], av, bv1.y);
        }
    }

    float bb0[8];
#pragma unroll
    for (int j = 0; j < 8; ++j) bb0[j] = be_s[n0 + j];

#pragma unroll
    for (int i = 0; i < 8; ++i) {
        int el = m0 + i;
        int s = src_s[el];
        int d = dst_s[el];
        const float* xr = x + (size_t)s * 128 + n0;
        float4 x1 = *(const float4*)xr;
        float4 x2 = *(const float4*)(xr + 4);
        float2 p0 = unpack2(acc[i][0]);
        float2 p1 = unpack2(acc[i][1]);
        float2 p2 = unpack2(acc[i][2]);
        float2 p3 = unpack2(acc[i][3]);
        float r0 = fmaxf(x1.x + p0.x + bb0[0], 0.f);
        float r1 = fmaxf(x1.y + p0.y + bb0[1], 0.f);
        float r2 = fmaxf(x1.z + p1.x + bb0[2], 0.f);
        float r3 = fmaxf(x1.w + p1.y + bb0[3], 0.f);
        float r4 = fmaxf(x2.x + p2.x + bb0[4], 0.f);
        float r5 = fmaxf(x2.y + p2.y + bb0[5], 0.f);
        float r6 = fmaxf(x2.z + p3.x + bb0[6], 0.f);
        float r7 = fmaxf(x2.w + p3.y + bb0[7], 0.f);
        float* dp = g_agg + (size_t)d * 128 + n0;
        asm volatile("red.global.add.v4.f32 [%0], {%1,%2,%3,%4};"
                     :: "l"(dp), "f"(r0), "f"(r1), "f"(r2), "f"(r3) : "memory");
        asm volatile("red.global.add.v4.f32 [%0], {%1,%2,%3,%4};"
                     :: "l"(dp + 4), "f"(r4), "f"(r5), "f"(r6), "f"(r7) : "memory");
    }
}

// ---------------------------------------------------------------------------
// 3) fused node MLP:  g_h = silu(g_agg @ W1 + b1) @ W2 + b2
//    AsT is k-major [128][132]; FFMA2 inner loops.
// ---------------------------------------------------------------------------
#define MLP_SMEM ((128 * 132 + 32 * 132) * 4)

extern "C" __global__ __launch_bounds__(256) void mlp_kernel(
    const float* __restrict__ W1, const float* __restrict__ b1,
    const float* __restrict__ W2, const float* __restrict__ b2) {
    extern __shared__ float smem[];
    float* AsT = smem;             // [128][132] : A[k][m] (k = feature)
    float* Ws = smem + 128 * 132;  // [32][132]  : W[k][n] chunk

    const int tid = threadIdx.x;
    const int r0 = blockIdx.x * 128;

    // load A transposed: 4096 float4s (node m, feature chunk k4)
    for (int i = tid; i < 4096; i += 256) {
        int m = i & 127, k4 = (i >> 7) * 4;
        int node = r0 + m;
        float4 v = make_float4(0.f, 0.f, 0.f, 0.f);
        if (node < Nn) v = *(const float4*)&g_agg[(size_t)node * 128 + k4];
        AsT[(k4 + 0) * 132 + m] = v.x;
        AsT[(k4 + 1) * 132 + m] = v.y;
        AsT[(k4 + 2) * 132 + m] = v.z;
        AsT[(k4 + 3) * 132 + m] = v.w;
    }

    const int tx = tid & 15, ty = tid >> 4;
    const int m0 = ty * 8, n0 = tx * 8;

    ull acc[8][4];
#pragma unroll
    for (int i = 0; i < 8; ++i)
#pragma unroll
        for (int j = 0; j < 4; ++j) acc[i][j] = 0ULL;

    // ---- layer 1 ----
    for (int kc = 0; kc < 128; kc += 32) {
        __syncthreads();
        for (int i = tid; i < 32 * 32; i += 256) {
            int kk = i >> 5, c4 = (i & 31) * 4;
            *(float4*)&Ws[kk * 132 + c4] = *(const float4*)&W1[(size_t)(kc + kk) * 128 + c4];
        }
        __syncthreads();
#pragma unroll
        for (int kk = 0; kk < 32; ++kk) {
            int k = kc + kk;
            float a[8];
            *(float4*)&a[0] = *(const float4*)&AsT[k * 132 + m0];
            *(float4*)&a[4] = *(const float4*)&AsT[k * 132 + m0 + 4];
            ulonglong2 bv0 = *(const ulonglong2*)&Ws[kk * 132 + n0];
            ulonglong2 bv1 = *(const ulonglong2*)&Ws[kk * 132 + n0 + 4];
#pragma unroll
            for (int i = 0; i < 8; ++i) {
                ull av = pack2(a[i], a[i]);
                ffma2(acc[i][0], av, bv0.x);
                ffma2(acc[i][1], av, bv0.y);
                ffma2(acc[i][2], av, bv1.x);
                ffma2(acc[i][3], av, bv1.y);
            }
        }
    }

    // mid = silu(acc + b1), written back transposed: AsT[feat][node]
    float bias1[8];
#pragma unroll
    for (int j = 0; j < 8; ++j) bias1[j] = b1[n0 + j];
    __syncthreads();
#pragma unroll
    for (int j = 0; j < 8; ++j) {
        float t[8];
#pragma unroll
        for (int i = 0; i < 8; ++i) {
            float2 p = unpack2(acc[i][j >> 1]);
            float v = ((j & 1) ? p.y : p.x) + bias1[j];
            t[i] = silu_f(v);
        }
        *(float4*)&AsT[(n0 + j) * 132 + m0] = *(float4*)&t[0];
        *(float4*)&AsT[(n0 + j) * 132 + m0 + 4] = *(float4*)&t[4];
    }
#pragma unroll
    for (int i = 0; i < 8; ++i)
#pragma unroll
        for (int j = 0; j < 4; ++j) acc[i][j] = 0ULL;

    // ---- layer 2 ----
    for (int kc = 0; kc < 128; kc += 32) {
        __syncthreads();
        for (int i = tid; i < 32 * 32; i += 256) {
            int kk = i >> 5, c4 = (i & 31) * 4;
            *(float4*)&Ws[kk * 132 + c4] = *(const float4*)&W2[(size_t)(kc + kk) * 128 + c4];
        }
        __syncthreads();
#pragma unroll
        for (int kk = 0; kk < 32; ++kk) {
            int k = kc + kk;
            float a[8];
            *(float4*)&a[0] = *(const float4*)&AsT[k * 132 + m0];
            *(float4*)&a[4] = *(const float4*)&AsT[k * 132 + m0 + 4];
            ulonglong2 bv0 = *(const ulonglong2*)&Ws[kk * 132 + n0];
            ulonglong2 bv1 = *(const ulonglong2*)&Ws[kk * 132 + n0 + 4];
#pragma unroll
            for (int i = 0; i < 8; ++i) {
                ull av = pack2(a[i], a[i]);
                ffma2(acc[i][0], av, bv0.x);
                ffma2(acc[i][1], av, bv0.y);
                ffma2(acc[i][2], av, bv1.x);
                ffma2(acc[i][3], av, bv1.y);
            }
        }
    }

    float bias2[8];
#pragma unroll
    for (int j = 0; j < 8; ++j) bias2[j] = b2[n0 + j];
#pragma unroll
    for (int i = 0; i < 8; ++i) {
        int node = r0 + m0 + i;
        if (node < Nn) {
            float t[8];
            float2 p0 = unpack2(acc[i][0]);
            float2 p1 = unpack2(acc[i][1]);
            float2 p2 = unpack2(acc[i][2]);
            float2 p3 = unpack2(acc[i][3]);
            t[0] = p0.x + bias2[0]; t[1] = p0.y + bias2[1];
            t[2] = p1.x + bias2[2]; t[3] = p1.y + bias2[3];
            t[4] = p2.x + bias2[4]; t[5] = p2.y + bias2[5];
            t[6] = p3.x + bias2[6]; t[7] = p3.y + bias2[7];
            *(float4*)&g_h[(size_t)node * 128 + n0] = *(float4*)&t[0];
            *(float4*)&g_h[(size_t)node * 128 + n0 + 4] = *(float4*)&t[4];
        }
    }
}

// ---------------------------------------------------------------------------
// 4) GraphNorm stats: one pass (sum, sumsq) per graph; batch is sorted.
// ---------------------------------------------------------------------------
__global__ void stats_kernel(const int* __restrict__ batch,
                             const float* __restrict__ ms) {
    __shared__ int bounds[2];
    const int g = blockIdx.x;
    if (threadIdx.x < 2) {
        int target = g + threadIdx.x;  // lower_bound(batch, target)
        int lo = 0, hi = Nn;
        while (lo < hi) {
            int mid = (lo + hi) >> 1;
            if (batch[mid] < target) lo = mid + 1; else hi = mid;
        }
        bounds[threadIdx.x] = lo;
    }
    __syncthreads();
    const int s = bounds[0], e = bounds[1];
    const int f = threadIdx.x;  // 128 threads

    float sum0 = 0.f, sq0 = 0.f, sum1 = 0.f, sq1 = 0.f;
    float sum2 = 0.f, sq2 = 0.f, sum3 = 0.f, sq3 = 0.f;
    int n = s;
    for (; n + 3 < e; n += 4) {
        float v0 = g_h[(size_t)n * 128 + f];
        float v1 = g_h[(size_t)(n + 1) * 128 + f];
        float v2 = g_h[(size_t)(n + 2) * 128 + f];
        float v3 = g_h[(size_t)(n + 3) * 128 + f];
        sum0 += v0; sq0 += v0 * v0;
        sum1 += v1; sq1 += v1 * v1;
        sum2 += v2; sq2 += v2 * v2;
        sum3 += v3; sq3 += v3 * v3;
    }
    for (; n < e; ++n) {
        float v0 = g_h[(size_t)n * 128 + f];
        sum0 += v0; sq0 += v0 * v0;
    }
    float sum = (sum0 + sum1) + (sum2 + sum3);
    float sq = (sq0 + sq1) + (sq2 + sq3);

    float c = fmaxf((float)(e - s), 1.f);
    float mean = sum / c;
    float m2 = sq / c;
    float msf = ms[f];
    float var = m2 - (2.f * msf - msf * msf) * mean * mean;
    var = fmaxf(var, 0.f);
    g_mean[g * 128 + f] = mean * msf;
    g_rstd[g * 128 + f] = rsqrtf(var + 1e-5f);
}

// ---------------------------------------------------------------------------
// 5) FiLM params: 8 graphs per block, te staged transposed, FFMA2.
// ---------------------------------------------------------------------------
__global__ __launch_bounds__(256) void film_kernel(
    const float* __restrict__ te,
    const float* __restrict__ Wg, const float* __restrict__ bg,
    const float* __restrict__ Wb, const float* __restrict__ bb) {
    __shared__ float tes[256][8];  // [k][g]
    const int tid = threadIdx.x;
    const int g0 = blockIdx.x * 8;

    // stage te transposed: 8 graphs x 256 dims = 512 float4 loads
    for (int i = tid; i < 512; i += 256) {
        int g = i >> 6, c4 = (i & 63) * 4;
        float4 v = *(const float4*)&te[(size_t)(g0 + g) * 256 + c4];
        tes[c4 + 0][g] = v.x;
        tes[c4 + 1][g] = v.y;
        tes[c4 + 2][g] = v.z;
        tes[c4 + 3][g] = v.w;
    }
    __syncthreads();

    const int f = tid & 127, half = tid >> 7;  // half 0: gamma, 1: beta
    const float* W = half ? Wb : Wg;

    ull acc[4];
#pragma unroll
    for (int j = 0; j < 4; ++j) acc[j] = 0ULL;

#pragma unroll 4
    for (int k = 0; k < 256; ++k) {
        float w = W[(size_t)k * 128 + f];
        ull wv = pack2(w, w);
        ulonglong2 t0 = *(const ulonglong2*)&tes[k][0];
        ulonglong2 t1 = *(const ulonglong2*)&tes[k][4];
        ffma2(acc[0], wv, t0.x);
        ffma2(acc[1], wv, t0.y);
        ffma2(acc[2], wv, t1.x);
        ffma2(acc[3], wv, t1.y);
    }

    float add = half ? bb[f] : (bg[f] + 1.0f);
    float* dst = half ? g_beta : g_gamma;
#pragma unroll
    for (int j = 0; j < 4; ++j) {
        float2 p = unpack2(acc[j]);
        dst[(g0 + 2 * j + 0) * 128 + f] = p.x + add;
        dst[(g0 + 2 * j + 1) * 128 + f] = p.y + add;
    }
}

// ---------------------------------------------------------------------------
// 6) final: out = x + silu(gamma*(gnw*((h - mean*ms)*rstd) + gnb) + beta)
// ---------------------------------------------------------------------------
__global__ void final_kernel(const float* __restrict__ x,
                             const int* __restrict__ batch,
                             const float* __restrict__ gnw,
                             const float* __restrict__ gnb,
                             float* __restrict__ out) {
    int i = blockIdx.x * blockDim.x + threadIdx.x;  // float4 index
    int n = i >> 5;
    int f4 = (i & 31) * 4;
    int g = batch[n];

    float4 h4 = *(float4*)&g_h[(size_t)n * 128 + f4];
    float4 x4 = *(const float4*)&x[(size_t)n * 128 + f4];
    float4 mn = *(float4*)&g_mean[g * 128 + f4];
    float4 rs = *(float4*)&g_rstd[g * 128 + f4];
    float4 gm = *(float4*)&g_gamma[g * 128 + f4];
    float4 bt = *(float4*)&g_beta[g * 128 + f4];
    float4 w4 = *(const float4*)&gnw[f4];
    float4 b4 = *(const float4*)&gnb[f4];

    float4 o;
    {
        float v = gm.x * (w4.x * ((h4.x - mn.x) * rs.x) + b4.x) + bt.x;
        o.x = x4.x + silu_f(v);
    }
    {
        float v = gm.y * (w4.y * ((h4.y - mn.y) * rs.y) + b4.y) + bt.y;
        o.y = x4.y + silu_f(v);
    }
    {
        float v = gm.z * (w4.z * ((h4.z - mn.z) * rs.z) + b4.z) + bt.z;
        o.z = x4.z + silu_f(v);
    }
    {
        float v = gm.w * (w4.w * ((h4.w - mn.w) * rs.w) + b4.w) + bt.w;
        o.w = x4.w + silu_f(v);
    }
    *(float4*)&out[(size_t)n * 128 + f4] = o;
}

// ---------------------------------------------------------------------------
extern "C" void kernel_launch(void* const* d_in, const int* in_sizes, int n_in,
                              void* d_out, int out_size) {
    const float* x   = (const float*)d_in[0];
    const int*   ei  = (const int*)d_in[1];
    const float* ea  = (const float*)d_in[2];
    const int*   bat = (const int*)d_in[3];
    const float* te  = (const float*)d_in[4];
    const float* We  = (const float*)d_in[5];
    const float* be  = (const float*)d_in[6];
    const float* W1  = (const float*)d_in[7];
    const float* b1  = (const float*)d_in[8];
    const float* W2  = (const float*)d_in[9];
    const float* b2  = (const float*)d_in[10];
    const float* gnw = (const float*)d_in[11];
    const float* gnb = (const float*)d_in[12];
    const float* gms = (const float*)d_in[13];
    const float* Wg  = (const float*)d_in[14];
    const float* bg  = (const float*)d_in[15];
    const float* Wb  = (const float*)d_in[16];
    const float* bb  = (const float*)d_in[17];
    float* out = (float*)d_out;

    cudaFuncSetAttribute((const void*)mlp_kernel,
                         cudaFuncAttributeMaxDynamicSharedMemorySize, MLP_SMEM);

    copy_kernel<<<12500, 256>>>(x);                       // N*H/4 = 3.2M float4
    edge_kernel<<<Ee / 128, 256>>>(x, ei, ea, We, be);    // 12500 blocks
    mlp_kernel<<<(Nn + 127) / 128, 256, MLP_SMEM>>>(W1, b1, W2, b2);
    film_kernel<<<Gg / 8, 256>>>(te, Wg, bg, Wb, bb);
    stats_kernel<<<Gg, 128>>>(bat, gms);
    final_kernel<<<12500, 256>>>(x, bat, gnw, gnb, out);  // N*H/4 float4
}

// round 6
// speedup vs baseline: 1.8624x; 1.5611x over previous
#include <cuda_runtime.h>
#include <cuda_bf16.h>
#include <cstdint>
#include <math.h>

#define Nn 100000
#define Ee 1600000
#define Hh 128
#define Gg 512
#define TDd 256
#define NTILES 12500   // Ee / 128
#define EK_GRID 296

typedef unsigned long long ull;

// Scratch (device globals — no allocation allowed)
__device__ float g_agg[(size_t)Nn * Hh];
__device__ float g_h[(size_t)Nn * Hh];
__device__ float g_mean[Gg * Hh];
__device__ float g_rstd[Gg * Hh];
__device__ float g_gamma[Gg * Hh];
__device__ float g_beta[Gg * Hh];

__device__ __forceinline__ float silu_f(float v) {
    return v * (1.0f / (1.0f + __expf(-v)));
}

// ---- packed f32x2 helpers --------------------------------------------------
__device__ __forceinline__ ull pack2(float x, float y) {
    ull r;
    asm("mov.b64 %0, {%1, %2};" : "=l"(r) : "f"(x), "f"(y));
    return r;
}
__device__ __forceinline__ void ffma2(ull& d, ull a, ull b) {
    asm("fma.rn.f32x2 %0, %1, %2, %0;" : "+l"(d) : "l"(a), "l"(b));
}
__device__ __forceinline__ float2 unpack2(ull v) {
    float2 r;
    asm("mov.b64 {%0, %1}, %2;" : "=f"(r.x), "=f"(r.y) : "l"(v));
    return r;
}

// ---- warp-level bf16 mma (sm_80+ baseline; OK on sm_100 non-a) -------------
__device__ __forceinline__ void mma_bf16(float* c, const uint32_t* a,
                                         uint32_t b0, uint32_t b1) {
    asm("mma.sync.aligned.m16n8k16.row.col.f32.bf16.bf16.f32 "
        "{%0,%1,%2,%3}, {%4,%5,%6,%7}, {%8,%9}, {%0,%1,%2,%3};"
        : "+f"(c[0]), "+f"(c[1]), "+f"(c[2]), "+f"(c[3])
        : "r"(a[0]), "r"(a[1]), "r"(a[2]), "r"(a[3]), "r"(b0), "r"(b1));
}

// split f32 -> (hi, lo) bf16 pairs, 8 values -> two uint4 (packed bf16x2)
__device__ __forceinline__ void cvt8(const float* v, uint4* hi, uint4* lo) {
    uint32_t h[4], l[4];
#pragma unroll
    for (int i = 0; i < 4; ++i) {
        float a = v[2 * i], b = v[2 * i + 1];
        __nv_bfloat16 ha = __float2bfloat16(a), hb = __float2bfloat16(b);
        __nv_bfloat16 la = __float2bfloat16(a - __bfloat162float(ha));
        __nv_bfloat16 lb = __float2bfloat16(b - __bfloat162float(hb));
        h[i] = ((uint32_t)__bfloat16_as_ushort(hb) << 16) | (uint32_t)__bfloat16_as_ushort(ha);
        l[i] = ((uint32_t)__bfloat16_as_ushort(lb) << 16) | (uint32_t)__bfloat16_as_ushort(la);
    }
    *hi = make_uint4(h[0], h[1], h[2], h[3]);
    *lo = make_uint4(l[0], l[1], l[2], l[3]);
}

// edge kernel smem layout (bytes); rows padded to 80B (40 bf16) -> conflict-free
#define SBE   0
#define SSRC  512
#define SDST  1024
#define SAHI  1536
#define SALO  (SAHI + 10240)
#define SBHI  (SALO + 10240)
#define SBLO  (SBHI + 10240)
#define EKSM  (SBLO + 10240)   // 42496 bytes (static shared, <48KB)

// ---------------------------------------------------------------------------
// 1) init: g_agg = x
// ---------------------------------------------------------------------------
__global__ void copy_kernel(const float* __restrict__ x) {
    size_t i = (size_t)blockIdx.x * blockDim.x + threadIdx.x;
    ((float4*)g_agg)[i] = ((const float4*)x)[i];
}

// ---------------------------------------------------------------------------
// 2) edge kernel: persistent split-bf16 mma.sync GEMM + gather/relu/scatter
//    tile: 128 edges(M) x 128 feat(N), K=32 (as 6 k16-steps: hh,hh,hl,hl,lh,lh)
// ---------------------------------------------------------------------------
__global__ __launch_bounds__(256, 2) void edge_kernel(
    const float* __restrict__ x, const int* __restrict__ ei,
    const float* __restrict__ ea, const float* __restrict__ We,
    const float* __restrict__ be) {
    __shared__ __align__(16) char smem[EKSM];
    const int tid = threadIdx.x;
    const int wid = tid >> 5;
    const int lane = tid & 31;

    float* be_s = (float*)(smem + SBE);
    int* src_s = (int*)(smem + SSRC);
    int* dst_s = (int*)(smem + SDST);

    if (tid < 128) be_s[tid] = be[tid];

    // stage B = We^T hi/lo, rows padded to 80B; once per persistent block
    {
        int n = tid >> 1;
        int ks = tid & 1;          // k-half: 0 -> k[0:16), 1 -> k[16:32)
        float w[16];
#pragma unroll
        for (int j = 0; j < 16; ++j) w[j] = We[(size_t)(ks * 16 + j) * 128 + n];
        uint4 h0, l0, h1, l1;
        cvt8(&w[0], &h0, &l0);
        cvt8(&w[8], &h1, &l1);
        char* bh = smem + SBHI + n * 80 + ks * 32;
        char* bl = smem + SBLO + n * 80 + ks * 32;
        *(uint4*)bh = h0;  *(uint4*)(bh + 16) = h1;
        *(uint4*)bl = l0;  *(uint4*)(bl + 16) = l1;
    }
    __syncthreads();

    const int g = lane >> 2;       // 0..7
    const int t = lane & 3;        // 0..3
    const int q = t >> 1;          // col quarter within 8-block
    const int odd = t & 1;
    const int mb = wid * 16;       // warp's M base

    for (int tile = blockIdx.x; tile < NTILES; tile += gridDim.x) {
        const int e0 = tile * 128;

        if (tid < 128) src_s[tid] = ei[e0 + tid];
        else           dst_s[tid - 128] = ei[Ee + e0 + (tid - 128)];

        // stage A = edge_attr tile hi/lo
        {
            int row = tid >> 1;
            int ks = tid & 1;
            const float* ap = ea + (size_t)(e0 + row) * 32 + ks * 16;
            float v[16];
            *(float4*)&v[0]  = *(const float4*)(ap + 0);
            *(float4*)&v[4]  = *(const float4*)(ap + 4);
            *(float4*)&v[8]  = *(const float4*)(ap + 8);
            *(float4*)&v[12] = *(const float4*)(ap + 12);
            uint4 h0, l0, h1, l1;
            cvt8(&v[0], &h0, &l0);
            cvt8(&v[8], &h1, &l1);
            char* ah = smem + SAHI + row * 80 + ks * 32;
            char* al = smem + SALO + row * 80 + ks * 32;
            *(uint4*)ah = h0;  *(uint4*)(ah + 16) = h1;
            *(uint4*)al = l0;  *(uint4*)(al + 16) = l1;
        }
        __syncthreads();

        // A fragments: [kstep][4 regs] for hi and lo
        uint32_t afh[2][4], afl[2][4];
        {
            const char* Ah = smem + SAHI + (mb + g) * 80 + t * 4;
            const char* Al = smem + SALO + (mb + g) * 80 + t * 4;
#pragma unroll
            for (int ks = 0; ks < 2; ++ks) {
                int o = ks * 32;
                afh[ks][0] = *(const uint32_t*)(Ah + o);
                afh[ks][1] = *(const uint32_t*)(Ah + o + 8 * 80);
                afh[ks][2] = *(const uint32_t*)(Ah + o + 16);
                afh[ks][3] = *(const uint32_t*)(Ah + o + 8 * 80 + 16);
                afl[ks][0] = *(const uint32_t*)(Al + o);
                afl[ks][1] = *(const uint32_t*)(Al + o + 8 * 80);
                afl[ks][2] = *(const uint32_t*)(Al + o + 16);
                afl[ks][3] = *(const uint32_t*)(Al + o + 8 * 80 + 16);
            }
        }

        float c[16][4];
#pragma unroll
        for (int nf = 0; nf < 16; ++nf) {
            c[nf][0] = 0.f; c[nf][1] = 0.f; c[nf][2] = 0.f; c[nf][3] = 0.f;
        }

#pragma unroll
        for (int nf = 0; nf < 16; ++nf) {
            const char* Bh = smem + SBHI + (nf * 8 + g) * 80 + t * 4;
            const char* Bl = smem + SBLO + (nf * 8 + g) * 80 + t * 4;
            uint32_t bh00 = *(const uint32_t*)(Bh);
            uint32_t bh01 = *(const uint32_t*)(Bh + 16);
            uint32_t bh10 = *(const uint32_t*)(Bh + 32);
            uint32_t bh11 = *(const uint32_t*)(Bh + 48);
            uint32_t bl00 = *(const uint32_t*)(Bl);
            uint32_t bl01 = *(const uint32_t*)(Bl + 16);
            uint32_t bl10 = *(const uint32_t*)(Bl + 32);
            uint32_t bl11 = *(const uint32_t*)(Bl + 48);
            mma_bf16(c[nf], afh[0], bh00, bh01);
            mma_bf16(c[nf], afh[1], bh10, bh11);
            mma_bf16(c[nf], afh[0], bl00, bl01);
            mma_bf16(c[nf], afh[1], bl10, bl11);
            mma_bf16(c[nf], afl[0], bh00, bh01);
            mma_bf16(c[nf], afl[1], bh10, bh11);
        }

        // epilogue: rows g and g+8; regroup C float2s into float4 via shfl_xor(1)
#pragma unroll
        for (int rs = 0; rs < 2; ++rs) {
            const int el = mb + g + rs * 8;
            const int s = src_s[el];
            const int d = dst_s[el];
            const float* xb = x + (size_t)s * 128;
            float* ob = g_agg + (size_t)d * 128;
#pragma unroll
            for (int p = 0; p < 8; ++p) {
                const int nfe = 2 * p, nfo = 2 * p + 1;
                float2 me, mo;
                me.x = c[nfe][rs * 2]; me.y = c[nfe][rs * 2 + 1];
                mo.x = c[nfo][rs * 2]; mo.y = c[nfo][rs * 2 + 1];
                // even t sends its odd-nf pair, odd t sends its even-nf pair
                ull send = odd ? pack2(me.x, me.y) : pack2(mo.x, mo.y);
                ull recv = __shfl_xor_sync(0xFFFFFFFFu, send, 1);
                float2 rv = unpack2(recv);
                const int nf = odd ? nfo : nfe;
                float2 lo2 = odd ? rv : me;   // cols 8nf+4q+0,1
                float2 hi2 = odd ? mo : rv;   // cols 8nf+4q+2,3
                const int col = nf * 8 + q * 4;
                float4 xv = *(const float4*)(xb + col);
                float4 bv = *(const float4*)&be_s[col];
                float r0 = fmaxf(xv.x + lo2.x + bv.x, 0.f);
                float r1 = fmaxf(xv.y + lo2.y + bv.y, 0.f);
                float r2 = fmaxf(xv.z + hi2.x + bv.z, 0.f);
                float r3 = fmaxf(xv.w + hi2.y + bv.w, 0.f);
                asm volatile("red.global.add.v4.f32 [%0], {%1,%2,%3,%4};"
                             :: "l"(ob + col), "f"(r0), "f"(r1), "f"(r2), "f"(r3)
                             : "memory");
            }
        }
        __syncthreads();
    }
}

// ---------------------------------------------------------------------------
// 3) fused node MLP (FFMA2) — unchanged from R2 (proven)
// ---------------------------------------------------------------------------
#define MLP_SMEM ((128 * 132 + 32 * 132) * 4)

extern "C" __global__ __launch_bounds__(256) void mlp_kernel(
    const float* __restrict__ W1, const float* __restrict__ b1,
    const float* __restrict__ W2, const float* __restrict__ b2) {
    extern __shared__ float fsm[];
    float* AsT = fsm;
    float* Ws = fsm + 128 * 132;

    const int tid = threadIdx.x;
    const int r0 = blockIdx.x * 128;

    for (int i = tid; i < 4096; i += 256) {
        int m = i & 127, k4 = (i >> 7) * 4;
        int node = r0 + m;
        float4 v = make_float4(0.f, 0.f, 0.f, 0.f);
        if (node < Nn) v = *(const float4*)&g_agg[(size_t)node * 128 + k4];
        AsT[(k4 + 0) * 132 + m] = v.x;
        AsT[(k4 + 1) * 132 + m] = v.y;
        AsT[(k4 + 2) * 132 + m] = v.z;
        AsT[(k4 + 3) * 132 + m] = v.w;
    }

    const int tx = tid & 15, ty = tid >> 4;
    const int m0 = ty * 8, n0 = tx * 8;

    ull acc[8][4];
#pragma unroll
    for (int i = 0; i < 8; ++i)
#pragma unroll
        for (int j = 0; j < 4; ++j) acc[i][j] = 0ULL;

    for (int kc = 0; kc < 128; kc += 32) {
        __syncthreads();
        for (int i = tid; i < 32 * 32; i += 256) {
            int kk = i >> 5, c4 = (i & 31) * 4;
            *(float4*)&Ws[kk * 132 + c4] = *(const float4*)&W1[(size_t)(kc + kk) * 128 + c4];
        }
        __syncthreads();
#pragma unroll
        for (int kk = 0; kk < 32; ++kk) {
            int k = kc + kk;
            float a[8];
            *(float4*)&a[0] = *(const float4*)&AsT[k * 132 + m0];
            *(float4*)&a[4] = *(const float4*)&AsT[k * 132 + m0 + 4];
            ulonglong2 bv0 = *(const ulonglong2*)&Ws[kk * 132 + n0];
            ulonglong2 bv1 = *(const ulonglong2*)&Ws[kk * 132 + n0 + 4];
#pragma unroll
            for (int i = 0; i < 8; ++i) {
                ull av = pack2(a[i], a[i]);
                ffma2(acc[i][0], av, bv0.x);
                ffma2(acc[i][1], av, bv0.y);
                ffma2(acc[i][2], av, bv1.x);
                ffma2(acc[i][3], av, bv1.y);
            }
        }
    }

    float bias1[8];
#pragma unroll
    for (int j = 0; j < 8; ++j) bias1[j] = b1[n0 + j];
    __syncthreads();
#pragma unroll
    for (int j = 0; j < 8; ++j) {
        float t[8];
#pragma unroll
        for (int i = 0; i < 8; ++i) {
            float2 p = unpack2(acc[i][j >> 1]);
            float v = ((j & 1) ? p.y : p.x) + bias1[j];
            t[i] = silu_f(v);
        }
        *(float4*)&AsT[(n0 + j) * 132 + m0] = *(float4*)&t[0];
        *(float4*)&AsT[(n0 + j) * 132 + m0 + 4] = *(float4*)&t[4];
    }
#pragma unroll
    for (int i = 0; i < 8; ++i)
#pragma unroll
        for (int j = 0; j < 4; ++j) acc[i][j] = 0ULL;

    for (int kc = 0; kc < 128; kc += 32) {
        __syncthreads();
        for (int i = tid; i < 32 * 32; i += 256) {
            int kk = i >> 5, c4 = (i & 31) * 4;
            *(float4*)&Ws[kk * 132 + c4] = *(const float4*)&W2[(size_t)(kc + kk) * 128 + c4];
        }
        __syncthreads();
#pragma unroll
        for (int kk = 0; kk < 32; ++kk) {
            int k = kc + kk;
            float a[8];
            *(float4*)&a[0] = *(const float4*)&AsT[k * 132 + m0];
            *(float4*)&a[4] = *(const float4*)&AsT[k * 132 + m0 + 4];
            ulonglong2 bv0 = *(const ulonglong2*)&Ws[kk * 132 + n0];
            ulonglong2 bv1 = *(const ulonglong2*)&Ws[kk * 132 + n0 + 4];
#pragma unroll
            for (int i = 0; i < 8; ++i) {
                ull av = pack2(a[i], a[i]);
                ffma2(acc[i][0], av, bv0.x);
                ffma2(acc[i][1], av, bv0.y);
                ffma2(acc[i][2], av, bv1.x);
                ffma2(acc[i][3], av, bv1.y);
            }
        }
    }

    float bias2[8];
#pragma unroll
    for (int j = 0; j < 8; ++j) bias2[j] = b2[n0 + j];
#pragma unroll
    for (int i = 0; i < 8; ++i) {
        int node = r0 + m0 + i;
        if (node < Nn) {
            float t[8];
            float2 p0 = unpack2(acc[i][0]);
            float2 p1 = unpack2(acc[i][1]);
            float2 p2 = unpack2(acc[i][2]);
            float2 p3 = unpack2(acc[i][3]);
            t[0] = p0.x + bias2[0]; t[1] = p0.y + bias2[1];
            t[2] = p1.x + bias2[2]; t[3] = p1.y + bias2[3];
            t[4] = p2.x + bias2[4]; t[5] = p2.y + bias2[5];
            t[6] = p3.x + bias2[6]; t[7] = p3.y + bias2[7];
            *(float4*)&g_h[(size_t)node * 128 + n0] = *(float4*)&t[0];
            *(float4*)&g_h[(size_t)node * 128 + n0 + 4] = *(float4*)&t[4];
        }
    }
}

// ---------------------------------------------------------------------------
// 4) GraphNorm stats
// ---------------------------------------------------------------------------
__global__ void stats_kernel(const int* __restrict__ batch,
                             const float* __restrict__ ms) {
    __shared__ int bounds[2];
    const int g = blockIdx.x;
    if (threadIdx.x < 2) {
        int target = g + threadIdx.x;
        int lo = 0, hi = Nn;
        while (lo < hi) {
            int mid = (lo + hi) >> 1;
            if (batch[mid] < target) lo = mid + 1; else hi = mid;
        }
        bounds[threadIdx.x] = lo;
    }
    __syncthreads();
    const int s = bounds[0], e = bounds[1];
    const int f = threadIdx.x;

    float sum0 = 0.f, sq0 = 0.f, sum1 = 0.f, sq1 = 0.f;
    float sum2 = 0.f, sq2 = 0.f, sum3 = 0.f, sq3 = 0.f;
    int n = s;
    for (; n + 3 < e; n += 4) {
        float v0 = g_h[(size_t)n * 128 + f];
        float v1 = g_h[(size_t)(n + 1) * 128 + f];
        float v2 = g_h[(size_t)(n + 2) * 128 + f];
        float v3 = g_h[(size_t)(n + 3) * 128 + f];
        sum0 += v0; sq0 += v0 * v0;
        sum1 += v1; sq1 += v1 * v1;
        sum2 += v2; sq2 += v2 * v2;
        sum3 += v3; sq3 += v3 * v3;
    }
    for (; n < e; ++n) {
        float v0 = g_h[(size_t)n * 128 + f];
        sum0 += v0; sq0 += v0 * v0;
    }
    float sum = (sum0 + sum1) + (sum2 + sum3);
    float sq = (sq0 + sq1) + (sq2 + sq3);

    float c = fmaxf((float)(e - s), 1.f);
    float mean = sum / c;
    float m2 = sq / c;
    float msf = ms[f];
    float var = m2 - (2.f * msf - msf * msf) * mean * mean;
    var = fmaxf(var, 0.f);
    g_mean[g * 128 + f] = mean * msf;
    g_rstd[g * 128 + f] = rsqrtf(var + 1e-5f);
}

// ---------------------------------------------------------------------------
// 5) FiLM params: 2 graphs per block (packed in f32x2), 256 blocks
// ---------------------------------------------------------------------------
__global__ __launch_bounds__(256) void film_kernel(
    const float* __restrict__ te,
    const float* __restrict__ Wg, const float* __restrict__ bg,
    const float* __restrict__ Wb, const float* __restrict__ bb) {
    __shared__ float tes[256][2];
    const int tid = threadIdx.x;
    const int g0 = blockIdx.x * 2;

    if (tid < 128) {
        int g = tid >> 6, c4 = (tid & 63) * 4;
        float4 v = *(const float4*)&te[(size_t)(g0 + g) * 256 + c4];
        tes[c4 + 0][g] = v.x;
        tes[c4 + 1][g] = v.y;
        tes[c4 + 2][g] = v.z;
        tes[c4 + 3][g] = v.w;
    }
    __syncthreads();

    const int f = tid & 127;
    const int half = tid >> 7;
    const float* W = half ? Wb : Wg;

    ull acc0 = 0ULL, acc1 = 0ULL;
#pragma unroll 8
    for (int k = 0; k < 256; k += 2) {
        float w0 = W[(size_t)k * 128 + f];
        float w1 = W[(size_t)(k + 1) * 128 + f];
        ull t0 = *reinterpret_cast<const ull*>(&tes[k][0]);
        ull t1 = *reinterpret_cast<const ull*>(&tes[k + 1][0]);
        ffma2(acc0, pack2(w0, w0), t0);
        ffma2(acc1, pack2(w1, w1), t1);
    }
    float2 p0 = unpack2(acc0), p1 = unpack2(acc1);
    float add = half ? bb[f] : (bg[f] + 1.0f);
    float* dst = half ? g_beta : g_gamma;
    dst[(g0 + 0) * 128 + f] = p0.x + p1.x + add;
    dst[(g0 + 1) * 128 + f] = p0.y + p1.y + add;
}

// ---------------------------------------------------------------------------
// 6) final elementwise
// ---------------------------------------------------------------------------
__global__ void final_kernel(const float* __restrict__ x,
                             const int* __restrict__ batch,
                             const float* __restrict__ gnw,
                             const float* __restrict__ gnb,
                             float* __restrict__ out) {
    int i = blockIdx.x * blockDim.x + threadIdx.x;
    int n = i >> 5;
    int f4 = (i & 31) * 4;
    int g = batch[n];

    float4 h4 = *(float4*)&g_h[(size_t)n * 128 + f4];
    float4 x4 = *(const float4*)&x[(size_t)n * 128 + f4];
    float4 mn = *(float4*)&g_mean[g * 128 + f4];
    float4 rs = *(float4*)&g_rstd[g * 128 + f4];
    float4 gm = *(float4*)&g_gamma[g * 128 + f4];
    float4 bt = *(float4*)&g_beta[g * 128 + f4];
    float4 w4 = *(const float4*)&gnw[f4];
    float4 b4 = *(const float4*)&gnb[f4];

    float4 o;
    o.x = x4.x + silu_f(gm.x * (w4.x * ((h4.x - mn.x) * rs.x) + b4.x) + bt.x);
    o.y = x4.y + silu_f(gm.y * (w4.y * ((h4.y - mn.y) * rs.y) + b4.y) + bt.y);
    o.z = x4.z + silu_f(gm.z * (w4.z * ((h4.z - mn.z) * rs.z) + b4.z) + bt.z);
    o.w = x4.w + silu_f(gm.w * (w4.w * ((h4.w - mn.w) * rs.w) + b4.w) + bt.w);
    *(float4*)&out[(size_t)n * 128 + f4] = o;
}

// ---------------------------------------------------------------------------
extern "C" void kernel_launch(void* const* d_in, const int* in_sizes, int n_in,
                              void* d_out, int out_size) {
    const float* x   = (const float*)d_in[0];
    const int*   ei  = (const int*)d_in[1];
    const float* ea  = (const float*)d_in[2];
    const int*   bat = (const int*)d_in[3];
    const float* te  = (const float*)d_in[4];
    const float* We  = (const float*)d_in[5];
    const float* be  = (const float*)d_in[6];
    const float* W1  = (const float*)d_in[7];
    const float* b1  = (const float*)d_in[8];
    const float* W2  = (const float*)d_in[9];
    const float* b2  = (const float*)d_in[10];
    const float* gnw = (const float*)d_in[11];
    const float* gnb = (const float*)d_in[12];
    const float* gms = (const float*)d_in[13];
    const float* Wg  = (const float*)d_in[14];
    const float* bg  = (const float*)d_in[15];
    const float* Wb  = (const float*)d_in[16];
    const float* bb  = (const float*)d_in[17];
    float* out = (float*)d_out;

    cudaFuncSetAttribute((const void*)mlp_kernel,
                         cudaFuncAttributeMaxDynamicSharedMemorySize, MLP_SMEM);

    copy_kernel<<<12500, 256>>>(x);
    edge_kernel<<<EK_GRID, 256>>>(x, ei, ea, We, be);
    mlp_kernel<<<(Nn + 127) / 128, 256, MLP_SMEM>>>(W1, b1, W2, b2);
    film_kernel<<<Gg / 2, 256>>>(te, Wg, bg, Wb, bb);
    stats_kernel<<<Gg, 128>>>(bat, gms);
    final_kernel<<<12500, 256>>>(x, bat, gnw, gnb, out);
}

// round 7
// speedup vs baseline: 2.1129x; 1.1345x over previous
#include <cuda_runtime.h>
#include <cuda_bf16.h>
#include <cstdint>
#include <math.h>

#define Nn 100000
#define Ee 1600000
#define Hh 128
#define Gg 512
#define TDd 256
#define NTILES 12500   // Ee / 128
#define EK_GRID 296

typedef unsigned long long ull;

// Scratch (device globals — no allocation allowed)
__device__ float g_agg[(size_t)Nn * Hh];
__device__ float g_h[(size_t)Nn * Hh];
__device__ float g_mean[Gg * Hh];
__device__ float g_rstd[Gg * Hh];
__device__ float g_gamma[Gg * Hh];
__device__ float g_beta[Gg * Hh];

__device__ __forceinline__ float silu_f(float v) {
    return v * (1.0f / (1.0f + __expf(-v)));
}

// ---- packed f32x2 helpers --------------------------------------------------
__device__ __forceinline__ ull pack2(float x, float y) {
    ull r;
    asm("mov.b64 %0, {%1, %2};" : "=l"(r) : "f"(x), "f"(y));
    return r;
}
__device__ __forceinline__ void ffma2(ull& d, ull a, ull b) {
    asm("fma.rn.f32x2 %0, %1, %2, %0;" : "+l"(d) : "l"(a), "l"(b));
}
__device__ __forceinline__ float2 unpack2(ull v) {
    float2 r;
    asm("mov.b64 {%0, %1}, %2;" : "=f"(r.x), "=f"(r.y) : "l"(v));
    return r;
}

// ---- warp-level bf16 mma (sm_80+ baseline; OK on sm_100 non-a) -------------
__device__ __forceinline__ void mma_bf16(float* c, const uint32_t* a,
                                         uint32_t b0, uint32_t b1) {
    asm("mma.sync.aligned.m16n8k16.row.col.f32.bf16.bf16.f32 "
        "{%0,%1,%2,%3}, {%4,%5,%6,%7}, {%8,%9}, {%0,%1,%2,%3};"
        : "+f"(c[0]), "+f"(c[1]), "+f"(c[2]), "+f"(c[3])
        : "r"(a[0]), "r"(a[1]), "r"(a[2]), "r"(a[3]), "r"(b0), "r"(b1));
}

// split f32 -> (hi, lo) bf16 pairs, 8 values -> two uint4 (packed bf16x2)
__device__ __forceinline__ void cvt8(const float* v, uint4* hi, uint4* lo) {
    uint32_t h[4], l[4];
#pragma unroll
    for (int i = 0; i < 4; ++i) {
        float a = v[2 * i], b = v[2 * i + 1];
        __nv_bfloat16 ha = __float2bfloat16(a), hb = __float2bfloat16(b);
        __nv_bfloat16 la = __float2bfloat16(a - __bfloat162float(ha));
        __nv_bfloat16 lb = __float2bfloat16(b - __bfloat162float(hb));
        h[i] = ((uint32_t)__bfloat16_as_ushort(hb) << 16) | (uint32_t)__bfloat16_as_ushort(ha);
        l[i] = ((uint32_t)__bfloat16_as_ushort(lb) << 16) | (uint32_t)__bfloat16_as_ushort(la);
    }
    *hi = make_uint4(h[0], h[1], h[2], h[3]);
    *lo = make_uint4(l[0], l[1], l[2], l[3]);
}

// split 2 floats -> packed bf16x2 hi and lo words
__device__ __forceinline__ void cvt2(float a, float b, uint32_t* hp, uint32_t* lp) {
    __nv_bfloat16 ha = __float2bfloat16(a), hb = __float2bfloat16(b);
    __nv_bfloat16 la = __float2bfloat16(a - __bfloat162float(ha));
    __nv_bfloat16 lb = __float2bfloat16(b - __bfloat162float(hb));
    *hp = ((uint32_t)__bfloat16_as_ushort(hb) << 16) | (uint32_t)__bfloat16_as_ushort(ha);
    *lp = ((uint32_t)__bfloat16_as_ushort(lb) << 16) | (uint32_t)__bfloat16_as_ushort(la);
}

// edge kernel smem layout (bytes); rows padded to 80B (40 bf16) -> conflict-free
#define SBE   0
#define SSRC  512
#define SDST  1024
#define SAHI  1536
#define SALO  (SAHI + 10240)
#define SBHI  (SALO + 10240)
#define SBLO  (SBHI + 10240)
#define EKSM  (SBLO + 10240)   // 42496 bytes (static shared, <48KB)

// ---------------------------------------------------------------------------
// 1) init: g_agg = x
// ---------------------------------------------------------------------------
__global__ void copy_kernel(const float* __restrict__ x) {
    size_t i = (size_t)blockIdx.x * blockDim.x + threadIdx.x;
    ((float4*)g_agg)[i] = ((const float4*)x)[i];
}

// ---------------------------------------------------------------------------
// 2) edge kernel: persistent split-bf16 mma.sync GEMM + gather/relu/scatter
// ---------------------------------------------------------------------------
__global__ __launch_bounds__(256, 2) void edge_kernel(
    const float* __restrict__ x, const int* __restrict__ ei,
    const float* __restrict__ ea, const float* __restrict__ We,
    const float* __restrict__ be) {
    __shared__ __align__(16) char smem[EKSM];
    const int tid = threadIdx.x;
    const int wid = tid >> 5;
    const int lane = tid & 31;

    float* be_s = (float*)(smem + SBE);
    int* src_s = (int*)(smem + SSRC);
    int* dst_s = (int*)(smem + SDST);

    if (tid < 128) be_s[tid] = be[tid];

    // stage B = We^T hi/lo, rows padded to 80B; once per persistent block
    {
        int n = tid >> 1;
        int ks = tid & 1;
        float w[16];
#pragma unroll
        for (int j = 0; j < 16; ++j) w[j] = We[(size_t)(ks * 16 + j) * 128 + n];
        uint4 h0, l0, h1, l1;
        cvt8(&w[0], &h0, &l0);
        cvt8(&w[8], &h1, &l1);
        char* bh = smem + SBHI + n * 80 + ks * 32;
        char* bl = smem + SBLO + n * 80 + ks * 32;
        *(uint4*)bh = h0;  *(uint4*)(bh + 16) = h1;
        *(uint4*)bl = l0;  *(uint4*)(bl + 16) = l1;
    }
    __syncthreads();

    const int g = lane >> 2;
    const int t = lane & 3;
    const int q = t >> 1;
    const int odd = t & 1;
    const int mb = wid * 16;

    for (int tile = blockIdx.x; tile < NTILES; tile += gridDim.x) {
        const int e0 = tile * 128;

        if (tid < 128) src_s[tid] = ei[e0 + tid];
        else           dst_s[tid - 128] = ei[Ee + e0 + (tid - 128)];

        {
            int row = tid >> 1;
            int ks = tid & 1;
            const float* ap = ea + (size_t)(e0 + row) * 32 + ks * 16;
            float v[16];
            *(float4*)&v[0]  = *(const float4*)(ap + 0);
            *(float4*)&v[4]  = *(const float4*)(ap + 4);
            *(float4*)&v[8]  = *(const float4*)(ap + 8);
            *(float4*)&v[12] = *(const float4*)(ap + 12);
            uint4 h0, l0, h1, l1;
            cvt8(&v[0], &h0, &l0);
            cvt8(&v[8], &h1, &l1);
            char* ah = smem + SAHI + row * 80 + ks * 32;
            char* al = smem + SALO + row * 80 + ks * 32;
            *(uint4*)ah = h0;  *(uint4*)(ah + 16) = h1;
            *(uint4*)al = l0;  *(uint4*)(al + 16) = l1;
        }
        __syncthreads();

        uint32_t afh[2][4], afl[2][4];
        {
            const char* Ah = smem + SAHI + (mb + g) * 80 + t * 4;
            const char* Al = smem + SALO + (mb + g) * 80 + t * 4;
#pragma unroll
            for (int ks = 0; ks < 2; ++ks) {
                int o = ks * 32;
                afh[ks][0] = *(const uint32_t*)(Ah + o);
                afh[ks][1] = *(const uint32_t*)(Ah + o + 8 * 80);
                afh[ks][2] = *(const uint32_t*)(Ah + o + 16);
                afh[ks][3] = *(const uint32_t*)(Ah + o + 8 * 80 + 16);
                afl[ks][0] = *(const uint32_t*)(Al + o);
                afl[ks][1] = *(const uint32_t*)(Al + o + 8 * 80);
                afl[ks][2] = *(const uint32_t*)(Al + o + 16);
                afl[ks][3] = *(const uint32_t*)(Al + o + 8 * 80 + 16);
            }
        }

        float c[16][4];
#pragma unroll
        for (int nf = 0; nf < 16; ++nf) {
            c[nf][0] = 0.f; c[nf][1] = 0.f; c[nf][2] = 0.f; c[nf][3] = 0.f;
        }

#pragma unroll
        for (int nf = 0; nf < 16; ++nf) {
            const char* Bh = smem + SBHI + (nf * 8 + g) * 80 + t * 4;
            const char* Bl = smem + SBLO + (nf * 8 + g) * 80 + t * 4;
            uint32_t bh00 = *(const uint32_t*)(Bh);
            uint32_t bh01 = *(const uint32_t*)(Bh + 16);
            uint32_t bh10 = *(const uint32_t*)(Bh + 32);
            uint32_t bh11 = *(const uint32_t*)(Bh + 48);
            uint32_t bl00 = *(const uint32_t*)(Bl);
            uint32_t bl01 = *(const uint32_t*)(Bl + 16);
            uint32_t bl10 = *(const uint32_t*)(Bl + 32);
            uint32_t bl11 = *(const uint32_t*)(Bl + 48);
            mma_bf16(c[nf], afh[0], bh00, bh01);
            mma_bf16(c[nf], afh[1], bh10, bh11);
            mma_bf16(c[nf], afh[0], bl00, bl01);
            mma_bf16(c[nf], afh[1], bl10, bl11);
            mma_bf16(c[nf], afl[0], bh00, bh01);
            mma_bf16(c[nf], afl[1], bh10, bh11);
        }

#pragma unroll
        for (int rs = 0; rs < 2; ++rs) {
            const int el = mb + g + rs * 8;
            const int s = src_s[el];
            const int d = dst_s[el];
            const float* xb = x + (size_t)s * 128;
            float* ob = g_agg + (size_t)d * 128;
#pragma unroll
            for (int p = 0; p < 8; ++p) {
                const int nfe = 2 * p, nfo = 2 * p + 1;
                float2 me, mo;
                me.x = c[nfe][rs * 2]; me.y = c[nfe][rs * 2 + 1];
                mo.x = c[nfo][rs * 2]; mo.y = c[nfo][rs * 2 + 1];
                ull send = odd ? pack2(me.x, me.y) : pack2(mo.x, mo.y);
                ull recv = __shfl_xor_sync(0xFFFFFFFFu, send, 1);
                float2 rv = unpack2(recv);
                const int nf = odd ? nfo : nfe;
                float2 lo2 = odd ? rv : me;
                float2 hi2 = odd ? mo : rv;
                const int col = nf * 8 + q * 4;
                float4 xv = *(const float4*)(xb + col);
                float4 bv = *(const float4*)&be_s[col];
                float r0 = fmaxf(xv.x + lo2.x + bv.x, 0.f);
                float r1 = fmaxf(xv.y + lo2.y + bv.y, 0.f);
                float r2 = fmaxf(xv.z + hi2.x + bv.z, 0.f);
                float r3 = fmaxf(xv.w + hi2.y + bv.w, 0.f);
                asm volatile("red.global.add.v4.f32 [%0], {%1,%2,%3,%4};"
                             :: "l"(ob + col), "f"(r0), "f"(r1), "f"(r2), "f"(r3)
                             : "memory");
            }
        }
        __syncthreads();
    }
}

// ---------------------------------------------------------------------------
// 3) fused node MLP on mma.sync split-bf16:
//    g_h = silu(g_agg @ W1 + b1) @ W2 + b2
//    tile: 128 nodes x 128 feats, K=128 in 4 chunks of 32.
// ---------------------------------------------------------------------------
#define MP 272            // A row pitch (136 bf16) -> conflict-free frag loads
#define MS_AHI 0
#define MS_ALO 34816
#define MS_WHI 69632
#define MS_WLO 79872
#define MS_B1  90112
#define MS_B2  90624
#define MLP_SMEM 91136

extern "C" __global__ __launch_bounds__(256) void mlp_kernel(
    const float* __restrict__ W1, const float* __restrict__ b1,
    const float* __restrict__ W2, const float* __restrict__ b2) {
    extern __shared__ __align__(16) char msm[];
    const int tid = threadIdx.x;
    const int wid = tid >> 5;
    const int lane = tid & 31;
    const int g = lane >> 2;
    const int t = lane & 3;
    const int q = t >> 1;
    const int odd = t & 1;
    const int mb = wid * 16;
    const int r0 = blockIdx.x * 128;

    float* b1s = (float*)(msm + MS_B1);
    float* b2s = (float*)(msm + MS_B2);
    if (tid < 128) b1s[tid] = b1[tid];
    else           b2s[tid - 128] = b2[tid - 128];

    // stage A = g_agg rows, full K=128, hi/lo split
    {
        int row = tid >> 1;
        int half = tid & 1;
        int node = r0 + row;
        const float* ap = g_agg + (size_t)node * 128 + half * 64;
#pragma unroll
        for (int gi = 0; gi < 4; ++gi) {
            float v[16];
            if (node < Nn) {
                *(float4*)&v[0]  = *(const float4*)(ap + gi * 16 + 0);
                *(float4*)&v[4]  = *(const float4*)(ap + gi * 16 + 4);
                *(float4*)&v[8]  = *(const float4*)(ap + gi * 16 + 8);
                *(float4*)&v[12] = *(const float4*)(ap + gi * 16 + 12);
            } else {
#pragma unroll
                for (int j = 0; j < 16; ++j) v[j] = 0.f;
            }
            uint4 h0, l0, h1, l1;
            cvt8(&v[0], &h0, &l0);
            cvt8(&v[8], &h1, &l1);
            uint32_t off = (uint32_t)row * MP + (uint32_t)(half * 64 + gi * 16) * 2;
            *(uint4*)(msm + MS_AHI + off)      = h0;
            *(uint4*)(msm + MS_AHI + off + 16) = h1;
            *(uint4*)(msm + MS_ALO + off)      = l0;
            *(uint4*)(msm + MS_ALO + off + 16) = l1;
        }
    }
    __syncthreads();

    float c[16][4];
#pragma unroll
    for (int nf = 0; nf < 16; ++nf) {
        c[nf][0] = 0.f; c[nf][1] = 0.f; c[nf][2] = 0.f; c[nf][3] = 0.f;
    }

    for (int lyr = 0; lyr < 2; ++lyr) {
        const float* W = (lyr == 0) ? W1 : W2;

        for (int kc = 0; kc < 128; kc += 32) {
            // stage W chunk transposed [n][k] hi/lo
            {
                int n = tid >> 1;
                int ks = tid & 1;
                float w[16];
#pragma unroll
                for (int j = 0; j < 16; ++j)
                    w[j] = W[(size_t)(kc + ks * 16 + j) * 128 + n];
                uint4 h0, l0, h1, l1;
                cvt8(&w[0], &h0, &l0);
                cvt8(&w[8], &h1, &l1);
                char* wh = msm + MS_WHI + n * 80 + ks * 32;
                char* wl = msm + MS_WLO + n * 80 + ks * 32;
                *(uint4*)wh = h0;  *(uint4*)(wh + 16) = h1;
                *(uint4*)wl = l0;  *(uint4*)(wl + 16) = l1;
            }
            __syncthreads();

            uint32_t afh[2][4], afl[2][4];
            {
                const char* Ah = msm + MS_AHI + (mb + g) * MP + kc * 2 + t * 4;
                const char* Al = msm + MS_ALO + (mb + g) * MP + kc * 2 + t * 4;
#pragma unroll
                for (int ks = 0; ks < 2; ++ks) {
                    int o = ks * 32;
                    afh[ks][0] = *(const uint32_t*)(Ah + o);
                    afh[ks][1] = *(const uint32_t*)(Ah + o + 8 * MP);
                    afh[ks][2] = *(const uint32_t*)(Ah + o + 16);
                    afh[ks][3] = *(const uint32_t*)(Ah + o + 8 * MP + 16);
                    afl[ks][0] = *(const uint32_t*)(Al + o);
                    afl[ks][1] = *(const uint32_t*)(Al + o + 8 * MP);
                    afl[ks][2] = *(const uint32_t*)(Al + o + 16);
                    afl[ks][3] = *(const uint32_t*)(Al + o + 8 * MP + 16);
                }
            }

#pragma unroll
            for (int nf = 0; nf < 16; ++nf) {
                const char* Bh = msm + MS_WHI + (nf * 8 + g) * 80 + t * 4;
                const char* Bl = msm + MS_WLO + (nf * 8 + g) * 80 + t * 4;
                uint32_t bh00 = *(const uint32_t*)(Bh);
                uint32_t bh01 = *(const uint32_t*)(Bh + 16);
                uint32_t bh10 = *(const uint32_t*)(Bh + 32);
                uint32_t bh11 = *(const uint32_t*)(Bh + 48);
                uint32_t bl00 = *(const uint32_t*)(Bl);
                uint32_t bl01 = *(const uint32_t*)(Bl + 16);
                uint32_t bl10 = *(const uint32_t*)(Bl + 32);
                uint32_t bl11 = *(const uint32_t*)(Bl + 48);
                mma_bf16(c[nf], afh[0], bh00, bh01);
                mma_bf16(c[nf], afh[1], bh10, bh11);
                mma_bf16(c[nf], afh[0], bl00, bl01);
                mma_bf16(c[nf], afh[1], bl10, bl11);
                mma_bf16(c[nf], afl[0], bh00, bh01);
                mma_bf16(c[nf], afl[1], bh10, bh11);
            }
            __syncthreads();
        }

        if (lyr == 0) {
            // mid = silu(c + b1); split hi/lo; write back into A buffers
#pragma unroll
            for (int nf = 0; nf < 16; ++nf) {
#pragma unroll
                for (int rs = 0; rs < 2; ++rs) {
                    int row = mb + g + rs * 8;
                    int col = nf * 8 + 2 * t;
                    float m0 = silu_f(c[nf][rs * 2] + b1s[col]);
                    float m1 = silu_f(c[nf][rs * 2 + 1] + b1s[col + 1]);
                    uint32_t hp, lp;
                    cvt2(m0, m1, &hp, &lp);
                    uint32_t off = (uint32_t)row * MP + (uint32_t)col * 2;
                    *(uint32_t*)(msm + MS_AHI + off) = hp;
                    *(uint32_t*)(msm + MS_ALO + off) = lp;
                    c[nf][rs * 2] = 0.f;
                    c[nf][rs * 2 + 1] = 0.f;
                }
            }
            __syncthreads();
        }
    }

    // epilogue: g_h = c + b2 (shfl regroup -> float4 stores)
#pragma unroll
    for (int rs = 0; rs < 2; ++rs) {
        const int node = r0 + mb + g + rs * 8;
        float* ob = g_h + (size_t)node * 128;
#pragma unroll
        for (int p = 0; p < 8; ++p) {
            const int nfe = 2 * p, nfo = 2 * p + 1;
            float2 me, mo;
            me.x = c[nfe][rs * 2]; me.y = c[nfe][rs * 2 + 1];
            mo.x = c[nfo][rs * 2]; mo.y = c[nfo][rs * 2 + 1];
            ull send = odd ? pack2(me.x, me.y) : pack2(mo.x, mo.y);
            ull recv = __shfl_xor_sync(0xFFFFFFFFu, send, 1);
            float2 rv = unpack2(recv);
            const int nf = odd ? nfo : nfe;
            float2 lo2 = odd ? rv : me;
            float2 hi2 = odd ? mo : rv;
            const int col = nf * 8 + q * 4;
            if (node < Nn) {
                float4 o;
                o.x = lo2.x + b2s[col + 0];
                o.y = lo2.y + b2s[col + 1];
                o.z = hi2.x + b2s[col + 2];
                o.w = hi2.y + b2s[col + 3];
                *(float4*)(ob + col) = o;
            }
        }
    }
}

// ---------------------------------------------------------------------------
// 4) GraphNorm stats
// ---------------------------------------------------------------------------
__global__ void stats_kernel(const int* __restrict__ batch,
                             const float* __restrict__ ms) {
    __shared__ int bounds[2];
    const int g = blockIdx.x;
    if (threadIdx.x < 2) {
        int target = g + threadIdx.x;
        int lo = 0, hi = Nn;
        while (lo < hi) {
            int mid = (lo + hi) >> 1;
            if (batch[mid] < target) lo = mid + 1; else hi = mid;
        }
        bounds[threadIdx.x] = lo;
    }
    __syncthreads();
    const int s = bounds[0], e = bounds[1];
    const int f = threadIdx.x;

    float sum0 = 0.f, sq0 = 0.f, sum1 = 0.f, sq1 = 0.f;
    float sum2 = 0.f, sq2 = 0.f, sum3 = 0.f, sq3 = 0.f;
    int n = s;
    for (; n + 3 < e; n += 4) {
        float v0 = g_h[(size_t)n * 128 + f];
        float v1 = g_h[(size_t)(n + 1) * 128 + f];
        float v2 = g_h[(size_t)(n + 2) * 128 + f];
        float v3 = g_h[(size_t)(n + 3) * 128 + f];
        sum0 += v0; sq0 += v0 * v0;
        sum1 += v1; sq1 += v1 * v1;
        sum2 += v2; sq2 += v2 * v2;
        sum3 += v3; sq3 += v3 * v3;
    }
    for (; n < e; ++n) {
        float v0 = g_h[(size_t)n * 128 + f];
        sum0 += v0; sq0 += v0 * v0;
    }
    float sum = (sum0 + sum1) + (sum2 + sum3);
    float sq = (sq0 + sq1) + (sq2 + sq3);

    float c = fmaxf((float)(e - s), 1.f);
    float mean = sum / c;
    float m2 = sq / c;
    float msf = ms[f];
    float var = m2 - (2.f * msf - msf * msf) * mean * mean;
    var = fmaxf(var, 0.f);
    g_mean[g * 128 + f] = mean * msf;
    g_rstd[g * 128 + f] = rsqrtf(var + 1e-5f);
}

// ---------------------------------------------------------------------------
// 5) FiLM params: 4 graphs per block, 128 blocks
// ---------------------------------------------------------------------------
__global__ __launch_bounds__(256) void film_kernel(
    const float* __restrict__ te,
    const float* __restrict__ Wg, const float* __restrict__ bg,
    const float* __restrict__ Wb, const float* __restrict__ bb) {
    __shared__ float tes[256][4];
    const int tid = threadIdx.x;
    const int g0 = blockIdx.x * 4;

    {
        int g = tid >> 6;
        int c4 = (tid & 63) * 4;
        float4 v = *(const float4*)&te[(size_t)(g0 + g) * 256 + c4];
        tes[c4 + 0][g] = v.x;
        tes[c4 + 1][g] = v.y;
        tes[c4 + 2][g] = v.z;
        tes[c4 + 3][g] = v.w;
    }
    __syncthreads();

    const int f = tid & 127;
    const int half = tid >> 7;
    const float* W = half ? Wb : Wg;

    ull a0 = 0ULL, a1 = 0ULL;
#pragma unroll 4
    for (int k = 0; k < 256; ++k) {
        float w = W[(size_t)k * 128 + f];
        ull wv = pack2(w, w);
        ffma2(a0, wv, *reinterpret_cast<const ull*>(&tes[k][0]));
        ffma2(a1, wv, *reinterpret_cast<const ull*>(&tes[k][2]));
    }
    float2 p0 = unpack2(a0), p1 = unpack2(a1);
    float add = half ? bb[f] : (bg[f] + 1.0f);
    float* dst = half ? g_beta : g_gamma;
    dst[(g0 + 0) * 128 + f] = p0.x + add;
    dst[(g0 + 1) * 128 + f] = p0.y + add;
    dst[(g0 + 2) * 128 + f] = p1.x + add;
    dst[(g0 + 3) * 128 + f] = p1.y + add;
}

// ---------------------------------------------------------------------------
// 6) final elementwise
// ---------------------------------------------------------------------------
__global__ void final_kernel(const float* __restrict__ x,
                             const int* __restrict__ batch,
                             const float* __restrict__ gnw,
                             const float* __restrict__ gnb,
                             float* __restrict__ out) {
    int i = blockIdx.x * blockDim.x + threadIdx.x;
    int n = i >> 5;
    int f4 = (i & 31) * 4;
    int g = batch[n];

    float4 h4 = *(float4*)&g_h[(size_t)n * 128 + f4];
    float4 x4 = *(const float4*)&x[(size_t)n * 128 + f4];
    float4 mn = *(float4*)&g_mean[g * 128 + f4];
    float4 rs = *(float4*)&g_rstd[g * 128 + f4];
    float4 gm = *(float4*)&g_gamma[g * 128 + f4];
    float4 bt = *(float4*)&g_beta[g * 128 + f4];
    float4 w4 = *(const float4*)&gnw[f4];
    float4 b4 = *(const float4*)&gnb[f4];

    float4 o;
    o.x = x4.x + silu_f(gm.x * (w4.x * ((h4.x - mn.x) * rs.x) + b4.x) + bt.x);
    o.y = x4.y + silu_f(gm.y * (w4.y * ((h4.y - mn.y) * rs.y) + b4.y) + bt.y);
    o.z = x4.z + silu_f(gm.z * (w4.z * ((h4.z - mn.z) * rs.z) + b4.z) + bt.z);
    o.w = x4.w + silu_f(gm.w * (w4.w * ((h4.w - mn.w) * rs.w) + b4.w) + bt.w);
    *(float4*)&out[(size_t)n * 128 + f4] = o;
}

// ---------------------------------------------------------------------------
extern "C" void kernel_launch(void* const* d_in, const int* in_sizes, int n_in,
                              void* d_out, int out_size) {
    const float* x   = (const float*)d_in[0];
    const int*   ei  = (const int*)d_in[1];
    const float* ea  = (const float*)d_in[2];
    const int*   bat = (const int*)d_in[3];
    const float* te  = (const float*)d_in[4];
    const float* We  = (const float*)d_in[5];
    const float* be  = (const float*)d_in[6];
    const float* W1  = (const float*)d_in[7];
    const float* b1  = (const float*)d_in[8];
    const float* W2  = (const float*)d_in[9];
    const float* b2  = (const float*)d_in[10];
    const float* gnw = (const float*)d_in[11];
    const float* gnb = (const float*)d_in[12];
    const float* gms = (const float*)d_in[13];
    const float* Wg  = (const float*)d_in[14];
    const float* bg  = (const float*)d_in[15];
    const float* Wb  = (const float*)d_in[16];
    const float* bb  = (const float*)d_in[17];
    float* out = (float*)d_out;

    cudaFuncSetAttribute((const void*)mlp_kernel,
                         cudaFuncAttributeMaxDynamicSharedMemorySize, MLP_SMEM);

    copy_kernel<<<12500, 256>>>(x);
    edge_kernel<<<EK_GRID, 256>>>(x, ei, ea, We, be);
    mlp_kernel<<<(Nn + 127) / 128, 256, MLP_SMEM>>>(W1, b1, W2, b2);
    film_kernel<<<Gg / 4, 256>>>(te, Wg, bg, Wb, bb);
    stats_kernel<<<Gg, 128>>>(bat, gms);
    final_kernel<<<12500, 256>>>(x, bat, gnw, gnb, out);
}

// round 8
// speedup vs baseline: 2.2324x; 1.0566x over previous
#include <cuda_runtime.h>
#include <cuda_bf16.h>
#include <cstdint>
#include <math.h>

#define Nn 100000
#define Ee 1600000
#define Hh 128
#define Gg 512
#define TDd 256
#define NTILES 12500   // Ee / 128
#define EK_GRID 296

typedef unsigned long long ull;

// Scratch (device globals — no allocation allowed)
__device__ float g_agg[(size_t)Nn * Hh];
__device__ float g_h[(size_t)Nn * Hh];
__device__ float g_mean[Gg * Hh];
__device__ float g_rstd[Gg * Hh];
__device__ float g_gamma[Gg * Hh];
__device__ float g_beta[Gg * Hh];

__device__ __forceinline__ float silu_f(float v) {
    return v * (1.0f / (1.0f + __expf(-v)));
}

// ---- packed f32x2 helpers --------------------------------------------------
__device__ __forceinline__ ull pack2(float x, float y) {
    ull r;
    asm("mov.b64 %0, {%1, %2};" : "=l"(r) : "f"(x), "f"(y));
    return r;
}
__device__ __forceinline__ void ffma2(ull& d, ull a, ull b) {
    asm("fma.rn.f32x2 %0, %1, %2, %0;" : "+l"(d) : "l"(a), "l"(b));
}
__device__ __forceinline__ float2 unpack2(ull v) {
    float2 r;
    asm("mov.b64 {%0, %1}, %2;" : "=f"(r.x), "=f"(r.y) : "l"(v));
    return r;
}

// ---- warp-level bf16 mma (sm_80+ baseline) ----------------------------------
__device__ __forceinline__ void mma_bf16(float* c, const uint32_t* a,
                                         uint32_t b0, uint32_t b1) {
    asm("mma.sync.aligned.m16n8k16.row.col.f32.bf16.bf16.f32 "
        "{%0,%1,%2,%3}, {%4,%5,%6,%7}, {%8,%9}, {%0,%1,%2,%3};"
        : "+f"(c[0]), "+f"(c[1]), "+f"(c[2]), "+f"(c[3])
        : "r"(a[0]), "r"(a[1]), "r"(a[2]), "r"(a[3]), "r"(b0), "r"(b1));
}

// split f32 -> (hi, lo) bf16 pairs, 8 values -> two uint4 (packed bf16x2)
__device__ __forceinline__ void cvt8(const float* v, uint4* hi, uint4* lo) {
    uint32_t h[4], l[4];
#pragma unroll
    for (int i = 0; i < 4; ++i) {
        float a = v[2 * i], b = v[2 * i + 1];
        __nv_bfloat16 ha = __float2bfloat16(a), hb = __float2bfloat16(b);
        __nv_bfloat16 la = __float2bfloat16(a - __bfloat162float(ha));
        __nv_bfloat16 lb = __float2bfloat16(b - __bfloat162float(hb));
        h[i] = ((uint32_t)__bfloat16_as_ushort(hb) << 16) | (uint32_t)__bfloat16_as_ushort(ha);
        l[i] = ((uint32_t)__bfloat16_as_ushort(lb) << 16) | (uint32_t)__bfloat16_as_ushort(la);
    }
    *hi = make_uint4(h[0], h[1], h[2], h[3]);
    *lo = make_uint4(l[0], l[1], l[2], l[3]);
}

// split 2 floats -> packed bf16x2 hi and lo words
__device__ __forceinline__ void cvt2(float a, float b, uint32_t* hp, uint32_t* lp) {
    __nv_bfloat16 ha = __float2bfloat16(a), hb = __float2bfloat16(b);
    __nv_bfloat16 la = __float2bfloat16(a - __bfloat162float(ha));
    __nv_bfloat16 lb = __float2bfloat16(b - __bfloat162float(hb));
    *hp = ((uint32_t)__bfloat16_as_ushort(hb) << 16) | (uint32_t)__bfloat16_as_ushort(ha);
    *lp = ((uint32_t)__bfloat16_as_ushort(lb) << 16) | (uint32_t)__bfloat16_as_ushort(la);
}

// Stage a (col n, k-half ks) strip of B/W into FRAGMENT-ORDERED smem:
// Bfrag[nf][lane] = uint4 {b00,b01,b10,b11}; this stager supplies words 2ks,2ks+1.
__device__ __forceinline__ void stage_bfrag(char* fh, char* fl, int n, int ks,
                                            const float* w /*16 vals*/) {
    uint4 h0, l0, h1, l1;
    cvt8(&w[0], &h0, &l0);   // h0[t] = pack(w[2t],w[2t+1])   -> word 2ks
    cvt8(&w[8], &h1, &l1);   // h1[t] = pack(w[2t+8],w[2t+9]) -> word 2ks+1
    const int nf = n >> 3, g = n & 7;
    uint32_t base = (uint32_t)(nf * 32 + g * 4) * 16 + (uint32_t)ks * 8;
    const uint32_t hw[4] = {h0.x, h0.y, h0.z, h0.w};
    const uint32_t hz[4] = {h1.x, h1.y, h1.z, h1.w};
    const uint32_t lw[4] = {l0.x, l0.y, l0.z, l0.w};
    const uint32_t lz[4] = {l1.x, l1.y, l1.z, l1.w};
#pragma unroll
    for (int t = 0; t < 4; ++t) {
        *(uint2*)(fh + base + t * 16) = make_uint2(hw[t], hz[t]);
        *(uint2*)(fl + base + t * 16) = make_uint2(lw[t], lz[t]);
    }
}

// edge kernel smem layout (bytes)
#define SBE   0
#define SSRC  512
#define SDST  1024
#define SAHI  1536
#define SALO  (SAHI + 10240)
#define SFBH  (SALO + 10240)          // B frag hi: 16nf*32lane*16B = 8192
#define SFBL  (SFBH + 8192)
#define EKSM  (SFBL + 8192)           // 38400 bytes (static shared)

// ---------------------------------------------------------------------------
// 1) init: g_agg = x
// ---------------------------------------------------------------------------
__global__ void copy_kernel(const float* __restrict__ x) {
    size_t i = (size_t)blockIdx.x * blockDim.x + threadIdx.x;
    ((float4*)g_agg)[i] = ((const float4*)x)[i];
}

// ---------------------------------------------------------------------------
// 2) edge kernel: persistent split-bf16 mma.sync GEMM + gather/relu/scatter
// ---------------------------------------------------------------------------
__global__ __launch_bounds__(256, 2) void edge_kernel(
    const float* __restrict__ x, const int* __restrict__ ei,
    const float* __restrict__ ea, const float* __restrict__ We,
    const float* __restrict__ be) {
    __shared__ __align__(16) char smem[EKSM];
    const int tid = threadIdx.x;
    const int wid = tid >> 5;
    const int lane = tid & 31;

    float* be_s = (float*)(smem + SBE);
    int* src_s = (int*)(smem + SSRC);
    int* dst_s = (int*)(smem + SDST);

    if (tid < 128) be_s[tid] = be[tid];

    // stage B = We^T hi/lo directly in fragment order; once per persistent block
    {
        int n = tid >> 1;
        int ks = tid & 1;
        float w[16];
#pragma unroll
        for (int j = 0; j < 16; ++j) w[j] = We[(size_t)(ks * 16 + j) * 128 + n];
        stage_bfrag(smem + SFBH, smem + SFBL, n, ks, w);
    }
    __syncthreads();

    const int g = lane >> 2;
    const int t = lane & 3;
    const int q = t >> 1;
    const int odd = t & 1;
    const int mb = wid * 16;

    for (int tile = blockIdx.x; tile < NTILES; tile += gridDim.x) {
        const int e0 = tile * 128;

        if (tid < 128) src_s[tid] = ei[e0 + tid];
        else           dst_s[tid - 128] = ei[Ee + e0 + (tid - 128)];

        {
            int row = tid >> 1;
            int ks = tid & 1;
            const float* ap = ea + (size_t)(e0 + row) * 32 + ks * 16;
            float v[16];
            *(float4*)&v[0]  = *(const float4*)(ap + 0);
            *(float4*)&v[4]  = *(const float4*)(ap + 4);
            *(float4*)&v[8]  = *(const float4*)(ap + 8);
            *(float4*)&v[12] = *(const float4*)(ap + 12);
            uint4 h0, l0, h1, l1;
            cvt8(&v[0], &h0, &l0);
            cvt8(&v[8], &h1, &l1);
            char* ah = smem + SAHI + row * 80 + ks * 32;
            char* al = smem + SALO + row * 80 + ks * 32;
            *(uint4*)ah = h0;  *(uint4*)(ah + 16) = h1;
            *(uint4*)al = l0;  *(uint4*)(al + 16) = l1;
        }
        __syncthreads();

        uint32_t afh[2][4], afl[2][4];
        {
            const char* Ah = smem + SAHI + (mb + g) * 80 + t * 4;
            const char* Al = smem + SALO + (mb + g) * 80 + t * 4;
#pragma unroll
            for (int ks = 0; ks < 2; ++ks) {
                int o = ks * 32;
                afh[ks][0] = *(const uint32_t*)(Ah + o);
                afh[ks][1] = *(const uint32_t*)(Ah + o + 8 * 80);
                afh[ks][2] = *(const uint32_t*)(Ah + o + 16);
                afh[ks][3] = *(const uint32_t*)(Ah + o + 8 * 80 + 16);
                afl[ks][0] = *(const uint32_t*)(Al + o);
                afl[ks][1] = *(const uint32_t*)(Al + o + 8 * 80);
                afl[ks][2] = *(const uint32_t*)(Al + o + 16);
                afl[ks][3] = *(const uint32_t*)(Al + o + 8 * 80 + 16);
            }
        }

        float c[16][4];
#pragma unroll
        for (int nf = 0; nf < 16; ++nf) {
            c[nf][0] = 0.f; c[nf][1] = 0.f; c[nf][2] = 0.f; c[nf][3] = 0.f;
        }

#pragma unroll
        for (int nf = 0; nf < 16; ++nf) {
            uint4 BH = *(const uint4*)(smem + SFBH + (uint32_t)(nf * 32 + lane) * 16);
            uint4 BL = *(const uint4*)(smem + SFBL + (uint32_t)(nf * 32 + lane) * 16);
            mma_bf16(c[nf], afh[0], BH.x, BH.y);
            mma_bf16(c[nf], afh[1], BH.z, BH.w);
            mma_bf16(c[nf], afh[0], BL.x, BL.y);
            mma_bf16(c[nf], afh[1], BL.z, BL.w);
            mma_bf16(c[nf], afl[0], BH.x, BH.y);
            mma_bf16(c[nf], afl[1], BH.z, BH.w);
        }

#pragma unroll
        for (int rs = 0; rs < 2; ++rs) {
            const int el = mb + g + rs * 8;
            const int s = src_s[el];
            const int d = dst_s[el];
            const float* xb = x + (size_t)s * 128;
            float* ob = g_agg + (size_t)d * 128;
#pragma unroll
            for (int p = 0; p < 8; ++p) {
                const int nfe = 2 * p, nfo = 2 * p + 1;
                float2 me, mo;
                me.x = c[nfe][rs * 2]; me.y = c[nfe][rs * 2 + 1];
                mo.x = c[nfo][rs * 2]; mo.y = c[nfo][rs * 2 + 1];
                ull send = odd ? pack2(me.x, me.y) : pack2(mo.x, mo.y);
                ull recv = __shfl_xor_sync(0xFFFFFFFFu, send, 1);
                float2 rv = unpack2(recv);
                const int nf = odd ? nfo : nfe;
                float2 lo2 = odd ? rv : me;
                float2 hi2 = odd ? mo : rv;
                const int col = nf * 8 + q * 4;
                float4 xv = *(const float4*)(xb + col);
                float4 bv = *(const float4*)&be_s[col];
                float r0 = fmaxf(xv.x + lo2.x + bv.x, 0.f);
                float r1 = fmaxf(xv.y + lo2.y + bv.y, 0.f);
                float r2 = fmaxf(xv.z + hi2.x + bv.z, 0.f);
                float r3 = fmaxf(xv.w + hi2.y + bv.w, 0.f);
                asm volatile("red.global.add.v4.f32 [%0], {%1,%2,%3,%4};"
                             :: "l"(ob + col), "f"(r0), "f"(r1), "f"(r2), "f"(r3)
                             : "memory");
            }
        }
        __syncthreads();
    }
}

// ---------------------------------------------------------------------------
// 3) fused node MLP on mma.sync split-bf16, W staged in fragment order
// ---------------------------------------------------------------------------
#define MP 272
#define MS_AHI 0
#define MS_ALO 34816
#define MS_WFH 69632          // 8192
#define MS_WFL 77824          // 8192
#define MS_B1  86016
#define MS_B2  86528
#define MLP_SMEM 87040

extern "C" __global__ __launch_bounds__(256) void mlp_kernel(
    const float* __restrict__ W1, const float* __restrict__ b1,
    const float* __restrict__ W2, const float* __restrict__ b2) {
    extern __shared__ __align__(16) char msm[];
    const int tid = threadIdx.x;
    const int wid = tid >> 5;
    const int lane = tid & 31;
    const int g = lane >> 2;
    const int t = lane & 3;
    const int q = t >> 1;
    const int odd = t & 1;
    const int mb = wid * 16;
    const int r0 = blockIdx.x * 128;

    float* b1s = (float*)(msm + MS_B1);
    float* b2s = (float*)(msm + MS_B2);
    if (tid < 128) b1s[tid] = b1[tid];
    else           b2s[tid - 128] = b2[tid - 128];

    // stage A = g_agg rows, full K=128, hi/lo split (272B pitch)
    {
        int row = tid >> 1;
        int half = tid & 1;
        int node = r0 + row;
        const float* ap = g_agg + (size_t)node * 128 + half * 64;
#pragma unroll
        for (int gi = 0; gi < 4; ++gi) {
            float v[16];
            if (node < Nn) {
                *(float4*)&v[0]  = *(const float4*)(ap + gi * 16 + 0);
                *(float4*)&v[4]  = *(const float4*)(ap + gi * 16 + 4);
                *(float4*)&v[8]  = *(const float4*)(ap + gi * 16 + 8);
                *(float4*)&v[12] = *(const float4*)(ap + gi * 16 + 12);
            } else {
#pragma unroll
                for (int j = 0; j < 16; ++j) v[j] = 0.f;
            }
            uint4 h0, l0, h1, l1;
            cvt8(&v[0], &h0, &l0);
            cvt8(&v[8], &h1, &l1);
            uint32_t off = (uint32_t)row * MP + (uint32_t)(half * 64 + gi * 16) * 2;
            *(uint4*)(msm + MS_AHI + off)      = h0;
            *(uint4*)(msm + MS_AHI + off + 16) = h1;
            *(uint4*)(msm + MS_ALO + off)      = l0;
            *(uint4*)(msm + MS_ALO + off + 16) = l1;
        }
    }
    __syncthreads();

    float c[16][4];
#pragma unroll
    for (int nf = 0; nf < 16; ++nf) {
        c[nf][0] = 0.f; c[nf][1] = 0.f; c[nf][2] = 0.f; c[nf][3] = 0.f;
    }

    for (int lyr = 0; lyr < 2; ++lyr) {
        const float* W = (lyr == 0) ? W1 : W2;

        for (int kc = 0; kc < 128; kc += 32) {
            // stage W chunk directly in fragment order
            {
                int n = tid >> 1;
                int ks = tid & 1;
                float w[16];
#pragma unroll
                for (int j = 0; j < 16; ++j)
                    w[j] = W[(size_t)(kc + ks * 16 + j) * 128 + n];
                stage_bfrag(msm + MS_WFH, msm + MS_WFL, n, ks, w);
            }
            __syncthreads();

            uint32_t afh[2][4], afl[2][4];
            {
                const char* Ah = msm + MS_AHI + (mb + g) * MP + kc * 2 + t * 4;
                const char* Al = msm + MS_ALO + (mb + g) * MP + kc * 2 + t * 4;
#pragma unroll
                for (int ks = 0; ks < 2; ++ks) {
                    int o = ks * 32;
                    afh[ks][0] = *(const uint32_t*)(Ah + o);
                    afh[ks][1] = *(const uint32_t*)(Ah + o + 8 * MP);
                    afh[ks][2] = *(const uint32_t*)(Ah + o + 16);
                    afh[ks][3] = *(const uint32_t*)(Ah + o + 8 * MP + 16);
                    afl[ks][0] = *(const uint32_t*)(Al + o);
                    afl[ks][1] = *(const uint32_t*)(Al + o + 8 * MP);
                    afl[ks][2] = *(const uint32_t*)(Al + o + 16);
                    afl[ks][3] = *(const uint32_t*)(Al + o + 8 * MP + 16);
                }
            }

#pragma unroll
            for (int nf = 0; nf < 16; ++nf) {
                uint4 BH = *(const uint4*)(msm + MS_WFH + (uint32_t)(nf * 32 + lane) * 16);
                uint4 BL = *(const uint4*)(msm + MS_WFL + (uint32_t)(nf * 32 + lane) * 16);
                mma_bf16(c[nf], afh[0], BH.x, BH.y);
                mma_bf16(c[nf], afh[1], BH.z, BH.w);
                mma_bf16(c[nf], afh[0], BL.x, BL.y);
                mma_bf16(c[nf], afh[1], BL.z, BL.w);
                mma_bf16(c[nf], afl[0], BH.x, BH.y);
                mma_bf16(c[nf], afl[1], BH.z, BH.w);
            }
            __syncthreads();
        }

        if (lyr == 0) {
            // mid = silu(c + b1); split hi/lo; write back into A buffers
#pragma unroll
            for (int nf = 0; nf < 16; ++nf) {
#pragma unroll
                for (int rs = 0; rs < 2; ++rs) {
                    int row = mb + g + rs * 8;
                    int col = nf * 8 + 2 * t;
                    float m0 = silu_f(c[nf][rs * 2] + b1s[col]);
                    float m1 = silu_f(c[nf][rs * 2 + 1] + b1s[col + 1]);
                    uint32_t hp, lp;
                    cvt2(m0, m1, &hp, &lp);
                    uint32_t off = (uint32_t)row * MP + (uint32_t)col * 2;
                    *(uint32_t*)(msm + MS_AHI + off) = hp;
                    *(uint32_t*)(msm + MS_ALO + off) = lp;
                    c[nf][rs * 2] = 0.f;
                    c[nf][rs * 2 + 1] = 0.f;
                }
            }
            __syncthreads();
        }
    }

    // epilogue: g_h = c + b2 (shfl regroup -> float4 stores)
#pragma unroll
    for (int rs = 0; rs < 2; ++rs) {
        const int node = r0 + mb + g + rs * 8;
        float* ob = g_h + (size_t)node * 128;
#pragma unroll
        for (int p = 0; p < 8; ++p) {
            const int nfe = 2 * p, nfo = 2 * p + 1;
            float2 me, mo;
            me.x = c[nfe][rs * 2]; me.y = c[nfe][rs * 2 + 1];
            mo.x = c[nfo][rs * 2]; mo.y = c[nfo][rs * 2 + 1];
            ull send = odd ? pack2(me.x, me.y) : pack2(mo.x, mo.y);
            ull recv = __shfl_xor_sync(0xFFFFFFFFu, send, 1);
            float2 rv = unpack2(recv);
            const int nf = odd ? nfo : nfe;
            float2 lo2 = odd ? rv : me;
            float2 hi2 = odd ? mo : rv;
            const int col = nf * 8 + q * 4;
            if (node < Nn) {
                float4 o;
                o.x = lo2.x + b2s[col + 0];
                o.y = lo2.y + b2s[col + 1];
                o.z = hi2.x + b2s[col + 2];
                o.w = hi2.y + b2s[col + 3];
                *(float4*)(ob + col) = o;
            }
        }
    }
}

// ---------------------------------------------------------------------------
// 4) GraphNorm stats
// ---------------------------------------------------------------------------
__global__ void stats_kernel(const int* __restrict__ batch,
                             const float* __restrict__ ms) {
    __shared__ int bounds[2];
    const int g = blockIdx.x;
    if (threadIdx.x < 2) {
        int target = g + threadIdx.x;
        int lo = 0, hi = Nn;
        while (lo < hi) {
            int mid = (lo + hi) >> 1;
            if (batch[mid] < target) lo = mid + 1; else hi = mid;
        }
        bounds[threadIdx.x] = lo;
    }
    __syncthreads();
    const int s = bounds[0], e = bounds[1];
    const int f = threadIdx.x;

    float sum0 = 0.f, sq0 = 0.f, sum1 = 0.f, sq1 = 0.f;
    float sum2 = 0.f, sq2 = 0.f, sum3 = 0.f, sq3 = 0.f;
    int n = s;
    for (; n + 3 < e; n += 4) {
        float v0 = g_h[(size_t)n * 128 + f];
        float v1 = g_h[(size_t)(n + 1) * 128 + f];
        float v2 = g_h[(size_t)(n + 2) * 128 + f];
        float v3 = g_h[(size_t)(n + 3) * 128 + f];
        sum0 += v0; sq0 += v0 * v0;
        sum1 += v1; sq1 += v1 * v1;
        sum2 += v2; sq2 += v2 * v2;
        sum3 += v3; sq3 += v3 * v3;
    }
    for (; n < e; ++n) {
        float v0 = g_h[(size_t)n * 128 + f];
        sum0 += v0; sq0 += v0 * v0;
    }
    float sum = (sum0 + sum1) + (sum2 + sum3);
    float sq = (sq0 + sq1) + (sq2 + sq3);

    float c = fmaxf((float)(e - s), 1.f);
    float mean = sum / c;
    float m2 = sq / c;
    float msf = ms[f];
    float var = m2 - (2.f * msf - msf * msf) * mean * mean;
    var = fmaxf(var, 0.f);
    g_mean[g * 128 + f] = mean * msf;
    g_rstd[g * 128 + f] = rsqrtf(var + 1e-5f);
}

// ---------------------------------------------------------------------------
// 5) FiLM params: 2 graphs per block (proven R6 config: 18.8us)
// ---------------------------------------------------------------------------
__global__ __launch_bounds__(256) void film_kernel(
    const float* __restrict__ te,
    const float* __restrict__ Wg, const float* __restrict__ bg,
    const float* __restrict__ Wb, const float* __restrict__ bb) {
    __shared__ float tes[256][2];
    const int tid = threadIdx.x;
    const int g0 = blockIdx.x * 2;

    if (tid < 128) {
        int g = tid >> 6, c4 = (tid & 63) * 4;
        float4 v = *(const float4*)&te[(size_t)(g0 + g) * 256 + c4];
        tes[c4 + 0][g] = v.x;
        tes[c4 + 1][g] = v.y;
        tes[c4 + 2][g] = v.z;
        tes[c4 + 3][g] = v.w;
    }
    __syncthreads();

    const int f = tid & 127;
    const int half = tid >> 7;
    const float* W = half ? Wb : Wg;

    ull acc0 = 0ULL, acc1 = 0ULL;
#pragma unroll 8
    for (int k = 0; k < 256; k += 2) {
        float w0 = W[(size_t)k * 128 + f];
        float w1 = W[(size_t)(k + 1) * 128 + f];
        ull t0 = *reinterpret_cast<const ull*>(&tes[k][0]);
        ull t1 = *reinterpret_cast<const ull*>(&tes[k + 1][0]);
        ffma2(acc0, pack2(w0, w0), t0);
        ffma2(acc1, pack2(w1, w1), t1);
    }
    float2 p0 = unpack2(acc0), p1 = unpack2(acc1);
    float add = half ? bb[f] : (bg[f] + 1.0f);
    float* dst = half ? g_beta : g_gamma;
    dst[(g0 + 0) * 128 + f] = p0.x + p1.x + add;
    dst[(g0 + 1) * 128 + f] = p0.y + p1.y + add;
}

// ---------------------------------------------------------------------------
// 6) final elementwise
// ---------------------------------------------------------------------------
__global__ void final_kernel(const float* __restrict__ x,
                             const int* __restrict__ batch,
                             const float* __restrict__ gnw,
                             const float* __restrict__ gnb,
                             float* __restrict__ out) {
    int i = blockIdx.x * blockDim.x + threadIdx.x;
    int n = i >> 5;
    int f4 = (i & 31) * 4;
    int g = batch[n];

    float4 h4 = *(float4*)&g_h[(size_t)n * 128 + f4];
    float4 x4 = *(const float4*)&x[(size_t)n * 128 + f4];
    float4 mn = *(float4*)&g_mean[g * 128 + f4];
    float4 rs = *(float4*)&g_rstd[g * 128 + f4];
    float4 gm = *(float4*)&g_gamma[g * 128 + f4];
    float4 bt = *(float4*)&g_beta[g * 128 + f4];
    float4 w4 = *(const float4*)&gnw[f4];
    float4 b4 = *(const float4*)&gnb[f4];

    float4 o;
    o.x = x4.x + silu_f(gm.x * (w4.x * ((h4.x - mn.x) * rs.x) + b4.x) + bt.x);
    o.y = x4.y + silu_f(gm.y * (w4.y * ((h4.y - mn.y) * rs.y) + b4.y) + bt.y);
    o.z = x4.z + silu_f(gm.z * (w4.z * ((h4.z - mn.z) * rs.z) + b4.z) + bt.z);
    o.w = x4.w + silu_f(gm.w * (w4.w * ((h4.w - mn.w) * rs.w) + b4.w) + bt.w);
    *(float4*)&out[(size_t)n * 128 + f4] = o;
}

// ---------------------------------------------------------------------------
extern "C" void kernel_launch(void* const* d_in, const int* in_sizes, int n_in,
                              void* d_out, int out_size) {
    const float* x   = (const float*)d_in[0];
    const int*   ei  = (const int*)d_in[1];
    const float* ea  = (const float*)d_in[2];
    const int*   bat = (const int*)d_in[3];
    const float* te  = (const float*)d_in[4];
    const float* We  = (const float*)d_in[5];
    const float* be  = (const float*)d_in[6];
    const float* W1  = (const float*)d_in[7];
    const float* b1  = (const float*)d_in[8];
    const float* W2  = (const float*)d_in[9];
    const float* b2  = (const float*)d_in[10];
    const float* gnw = (const float*)d_in[11];
    const float* gnb = (const float*)d_in[12];
    const float* gms = (const float*)d_in[13];
    const float* Wg  = (const float*)d_in[14];
    const float* bg  = (const float*)d_in[15];
    const float* Wb  = (const float*)d_in[16];
    const float* bb  = (const float*)d_in[17];
    float* out = (float*)d_out;

    cudaFuncSetAttribute((const void*)mlp_kernel,
                         cudaFuncAttributeMaxDynamicSharedMemorySize, MLP_SMEM);

    copy_kernel<<<12500, 256>>>(x);
    edge_kernel<<<EK_GRID, 256>>>(x, ei, ea, We, be);
    mlp_kernel<<<(Nn + 127) / 128, 256, MLP_SMEM>>>(W1, b1, W2, b2);
    film_kernel<<<Gg / 2, 256>>>(te, Wg, bg, Wb, bb);
    stats_kernel<<<Gg, 128>>>(bat, gms);
    final_kernel<<<12500, 256>>>(x, bat, gnw, gnb, out);
}